// round 7
// baseline (speedup 1.0000x reference)
#include <cuda_runtime.h>
#include <cstdint>

#define NMAX   20000
#define EMAX   160000
#define D      512
#define NBUK   11
#define TM     128
#define MAXT   ((NMAX + TM - 1) / TM + NBUK)   // 168
#define BN_EPS 1e-5f

#define TN  128
#define TK  32
#define APITCH 36    // words; 144B rows, 16B-aligned, conflict-free frag reads
#define BPITCH 136   // words; 544B rows, 16B-aligned, conflict-free frag reads
#define A_WORDS (TM * APITCH)            // 4608
#define B_WORDS (TK * BPITCH)            // 4352
#define STAGES 3
#define STAGE_WORDS (A_WORDS + B_WORDS)  // 8960 words = 35840 B (16B-aligned)
#define SMEM_WORDS (STAGES * STAGE_WORDS)
#define SMEM_BYTES (SMEM_WORDS*4 + TM*4) // buffers + perm_s = 108032 B

// ---------------- scratch (device globals; no allocation allowed) -------------
__device__ int   g_deg[NMAX];
__device__ int   g_off[NMAX + 1];
__device__ int   g_cur[NMAX];
__device__ int   g_csr[EMAX];
__device__ int   g_boff[NBUK + 1];
__device__ int   g_bcur[NBUK];
__device__ int   g_perm[NMAX];
__device__ int   g_tile_bucket[MAXT];
__device__ int   g_tile_row[MAXT];
__device__ int   g_tile_rows[MAXT];
__device__ int   g_ntiles;
__device__ float g_h[(size_t)NMAX * D];     // neighbor sums
__device__ float g_x[(size_t)NMAX * D];     // pre-BN linear output
__device__ float g_sum[D], g_sumsq[D], g_scale[D], g_shift[D];

// ---------------- helpers -----------------------------------------------------
__device__ __forceinline__ void mma_tf32(float c[4], const uint32_t a[4],
                                         const uint32_t b[2]) {
    asm volatile(
        "mma.sync.aligned.m16n8k8.row.col.f32.tf32.tf32.f32 "
        "{%0,%1,%2,%3}, {%4,%5,%6,%7}, {%8,%9}, {%0,%1,%2,%3};\n"
        : "+f"(c[0]), "+f"(c[1]), "+f"(c[2]), "+f"(c[3])
        : "r"(a[0]), "r"(a[1]), "r"(a[2]), "r"(a[3]), "r"(b[0]), "r"(b[1]));
}

__device__ __forceinline__ void cp_async16(uint32_t saddr, const void* gaddr,
                                           int src_bytes) {
    asm volatile("cp.async.cg.shared.global [%0], [%1], 16, %2;\n"
                 :: "r"(saddr), "l"(gaddr), "r"(src_bytes));
}
__device__ __forceinline__ void cp_commit() {
    asm volatile("cp.async.commit_group;\n");
}
__device__ __forceinline__ void cp_wait1() {
    asm volatile("cp.async.wait_group 1;\n");
}

// ---------------- setup kernels ------------------------------------------------
__global__ void k_degcount(const int* __restrict__ dst, int e) {
    int i = blockIdx.x * blockDim.x + threadIdx.x;
    if (i < e) atomicAdd(&g_deg[dst[i]], 1);
}

// blocked 3-phase scan (20 elems/thread) + bucket histogram + tile map, one block
__global__ void k_scan(int n) {
    __shared__ int wsum[32];
    __shared__ int bc[NBUK];
    int t = threadIdx.x, lane = t & 31, w = t >> 5;
    if (t < NBUK) bc[t] = 0;
    int pt = (n + 1023) >> 10;                 // <= 20 for NMAX
    int base = t * pt;
    int vals[20];
    int local = 0;
#pragma unroll 1
    for (int i = 0; i < pt; i++) {
        int idx = base + i;
        int v = (idx < n) ? g_deg[idx] : 0;
        vals[i] = v;
        local += v;
    }
    // inclusive scan of per-thread sums
    int x = local;
#pragma unroll
    for (int o = 1; o < 32; o <<= 1) {
        int y = __shfl_up_sync(0xffffffffu, x, o);
        if (lane >= o) x += y;
    }
    if (lane == 31) wsum[w] = x;
    __syncthreads();
    if (w == 0) {
        int s = wsum[lane];
#pragma unroll
        for (int o = 1; o < 32; o <<= 1) {
            int y = __shfl_up_sync(0xffffffffu, s, o);
            if (lane >= o) s += y;
        }
        wsum[lane] = s;
    }
    __syncthreads();
    int run = (x - local) + ((w > 0) ? wsum[w - 1] : 0);   // exclusive prefix
#pragma unroll 1
    for (int i = 0; i < pt; i++) {
        int idx = base + i;
        if (idx < n) {
            g_off[idx] = run;
            g_cur[idx] = run;
            run += vals[i];
        }
    }
    if (t == 0) g_off[n] = wsum[31];
    // degree histogram from the register copy
#pragma unroll 1
    for (int i = 0; i < pt; i++) {
        int idx = base + i;
        if (idx < n) {
            int dd = vals[i];
            if (dd > NBUK - 1) dd = NBUK - 1;
            atomicAdd(&bc[dd], 1);
        }
    }
    __syncthreads();
    if (t == 0) {
        int acc = 0;
        for (int dd = 0; dd < NBUK; dd++) {
            g_boff[dd] = acc;
            acc += bc[dd];
        }
        g_boff[NBUK] = acc;
        int tt = 0;
        for (int dd = 0; dd < NBUK; dd++) {
            int c = bc[dd], o = g_boff[dd];
            for (int r = 0; r < c; r += TM) {
                g_tile_bucket[tt] = dd;
                g_tile_row[tt]    = o + r;
                g_tile_rows[tt]   = (c - r < TM) ? (c - r) : TM;
                tt++;
            }
        }
        g_ntiles = tt;
    }
}

// CSR fill (2 edges/thread) + bucket fill (merged)
__global__ void k_fill(const int* __restrict__ src, const int* __restrict__ dst,
                       int e, int n) {
    int i = blockIdx.x * blockDim.x + threadIdx.x;
    int e2 = (e + 1) >> 1;
    if (i < e2) {
        int j0 = 2 * i, j1 = 2 * i + 1;
        int d0 = dst[j0], s0 = src[j0];
        int d1 = -1, s1 = 0;
        if (j1 < e) { d1 = dst[j1]; s1 = src[j1]; }
        int p0 = atomicAdd(&g_cur[d0], 1);
        int p1 = (d1 >= 0) ? atomicAdd(&g_cur[d1], 1) : 0;
        g_csr[p0] = s0;
        if (d1 >= 0) g_csr[p1] = s1;
    } else {
        int v = i - e2;
        if (v < n) {
            int dd = g_deg[v];
            if (dd > NBUK - 1) dd = NBUK - 1;
            int pos = g_boff[dd] + atomicAdd(&g_bcur[dd], 1);
            g_perm[pos] = v;
        }
    }
}

// ---------------- neighbor sum (MLP 4) --------------------------------------------
__global__ void k_nbrsum(const float* __restrict__ feats) {
    int v = blockIdx.x;
    int t = threadIdx.x;
    float4 acc = make_float4(0.f, 0.f, 0.f, 0.f);
    int beg = g_off[v], end = g_off[v + 1];
    int j = beg;
    for (; j + 4 <= end; j += 4) {
        int u0 = g_csr[j], u1 = g_csr[j + 1], u2 = g_csr[j + 2], u3 = g_csr[j + 3];
        float4 w0 = *reinterpret_cast<const float4*>(feats + (size_t)u0 * D + t * 4);
        float4 w1 = *reinterpret_cast<const float4*>(feats + (size_t)u1 * D + t * 4);
        float4 w2 = *reinterpret_cast<const float4*>(feats + (size_t)u2 * D + t * 4);
        float4 w3 = *reinterpret_cast<const float4*>(feats + (size_t)u3 * D + t * 4);
        acc.x += (w0.x + w1.x) + (w2.x + w3.x);
        acc.y += (w0.y + w1.y) + (w2.y + w3.y);
        acc.z += (w0.z + w1.z) + (w2.z + w3.z);
        acc.w += (w0.w + w1.w) + (w2.w + w3.w);
    }
    for (; j < end; j++) {
        int u = g_csr[j];
        float4 w = *reinterpret_cast<const float4*>(feats + (size_t)u * D + t * 4);
        acc.x += w.x; acc.y += w.y; acc.z += w.z; acc.w += w.w;
    }
    *reinterpret_cast<float4*>(g_h + (size_t)v * D + t * 4) = acc;
}

// ---------------- bucketed tf32 GEMM, 3-stage cp.async, occ 2 --------------------
// x[node] = [h|feats](K=1024) @ [Wl[d];Wr[d]](1024x512) + bl[d]; BN stats fused.
__global__ __launch_bounds__(256, 2)
void k_gemm(const float* __restrict__ feats, const float* __restrict__ Wl,
            const float* __restrict__ Wr, const float* __restrict__ bl) {
    int tileId = blockIdx.y;
    if (tileId >= g_ntiles) return;
    int d     = g_tile_bucket[tileId];
    int row0  = g_tile_row[tileId];
    int nrows = g_tile_rows[tileId];
    int n0    = blockIdx.x * TN;

    extern __shared__ float smem[];
    int* perm_s = (int*)(smem + SMEM_WORDS);

    int tid  = threadIdx.x;
    int lane = tid & 31;
    int warp = tid >> 5;
    int grp  = lane >> 2;
    int tig  = lane & 3;
    int wrow0 = (warp & 1) * 64;
    int wcol0 = (warp >> 1) * 32;

    if (tid < TM) perm_s[tid] = (tid < nrows) ? g_perm[row0 + tid] : -1;
    __syncthreads();

    // per-thread load coordinates
    int a_row = tid >> 3, a_f4 = tid & 7;     // + p*32 rows
    int b_kr  = tid >> 5, b_f4 = tid & 31;    // + p*8 k-rows

    uint32_t a_s[4], b_s[4];
    size_t a_goff[4];                          // ELEMENT offsets into g_h/feats
    int a_valid[4];
#pragma unroll
    for (int p = 0; p < 4; p++) {
        int row = a_row + p * 32;
        int node = perm_s[row];
        a_valid[p] = (node >= 0) ? 16 : 0;
        if (node < 0) node = 0;
        a_goff[p] = (size_t)node * D + (size_t)(a_f4 * 4);
        a_s[p] = (uint32_t)__cvta_generic_to_shared(
            &smem[row * APITCH + a_f4 * 4]);
        b_s[p] = (uint32_t)__cvta_generic_to_shared(
            &smem[A_WORDS + (b_kr + p * 8) * BPITCH + b_f4 * 4]);
    }
    const size_t wbase = (size_t)d * D * D + (size_t)n0;

    auto load_stage = [&](int kk, int stg) {
        const float* aptr = (kk < 512) ? g_h : feats;
        const float* wptr = (kk < 512) ? Wl : Wr;
        int kb = kk & 511;
        uint32_t soff = (uint32_t)(stg * (STAGE_WORDS * 4));
#pragma unroll
        for (int p = 0; p < 4; p++)
            cp_async16(a_s[p] + soff, aptr + a_goff[p] + kb, a_valid[p]);
#pragma unroll
        for (int p = 0; p < 4; p++)
            cp_async16(b_s[p] + soff,
                       wptr + wbase + (size_t)(kb + b_kr + p * 8) * D + b_f4 * 4, 16);
    };

    float acc[4][4][4];
#pragma unroll
    for (int mi = 0; mi < 4; mi++)
#pragma unroll
        for (int ni = 0; ni < 4; ni++)
#pragma unroll
            for (int q = 0; q < 4; q++) acc[mi][ni][q] = 0.f;

    load_stage(0, 0); cp_commit();
    load_stage(TK, 1); cp_commit();

    int stage = 0;
#pragma unroll 1
    for (int kt = 0; kt < 1024 / TK; kt++) {
        cp_wait1();
        __syncthreads();
        // prefetch stage kt+2 into the buffer last read at iteration kt-1
        if (kt + 2 < 1024 / TK) {
            int nstg = stage + 2; if (nstg >= STAGES) nstg -= STAGES;
            load_stage((kt + 2) * TK, nstg);
        }
        cp_commit();

        const uint32_t* As = (const uint32_t*)(smem + stage * STAGE_WORDS);
        const uint32_t* Bs = As + A_WORDS;
#pragma unroll
        for (int k8 = 0; k8 < TK; k8 += 8) {
            uint32_t af[4][4], bf[4][2];
#pragma unroll
            for (int mi = 0; mi < 4; mi++) {
                int r0 = wrow0 + mi * 16 + grp;
                af[mi][0] = As[r0 * APITCH + k8 + tig];
                af[mi][1] = As[(r0 + 8) * APITCH + k8 + tig];
                af[mi][2] = As[r0 * APITCH + k8 + tig + 4];
                af[mi][3] = As[(r0 + 8) * APITCH + k8 + tig + 4];
            }
#pragma unroll
            for (int ni = 0; ni < 4; ni++) {
                int c0 = wcol0 + ni * 8 + grp;
                bf[ni][0] = Bs[(k8 + tig) * BPITCH + c0];
                bf[ni][1] = Bs[(k8 + tig + 4) * BPITCH + c0];
            }
#pragma unroll
            for (int mi = 0; mi < 4; mi++)
#pragma unroll
                for (int ni = 0; ni < 4; ni++)
                    mma_tf32(acc[mi][ni], af[mi], bf[ni]);
        }
        stage = stage + 1; if (stage >= STAGES) stage = 0;
    }

    // epilogue: bias add, store, fused BN column sums
    float2 bias[4];
#pragma unroll
    for (int ni = 0; ni < 4; ni++)
        bias[ni] = *reinterpret_cast<const float2*>(
            bl + (size_t)d * D + n0 + wcol0 + ni * 8 + 2 * tig);

    float s_sum[4][2] = {}, s_sq[4][2] = {};
#pragma unroll
    for (int mi = 0; mi < 4; mi++) {
        int r0 = wrow0 + mi * 16 + grp;
        int node0 = perm_s[r0];
        int node1 = perm_s[r0 + 8];
#pragma unroll
        for (int ni = 0; ni < 4; ni++) {
            int cc = wcol0 + ni * 8 + 2 * tig;
            float v0x = acc[mi][ni][0] + bias[ni].x;
            float v0y = acc[mi][ni][1] + bias[ni].y;
            float v1x = acc[mi][ni][2] + bias[ni].x;
            float v1y = acc[mi][ni][3] + bias[ni].y;
            if (node0 >= 0) {
                float2 v; v.x = v0x; v.y = v0y;
                *reinterpret_cast<float2*>(g_x + (size_t)node0 * D + n0 + cc) = v;
                s_sum[ni][0] += v0x; s_sq[ni][0] += v0x * v0x;
                s_sum[ni][1] += v0y; s_sq[ni][1] += v0y * v0y;
            }
            if (node1 >= 0) {
                float2 v; v.x = v1x; v.y = v1y;
                *reinterpret_cast<float2*>(g_x + (size_t)node1 * D + n0 + cc) = v;
                s_sum[ni][0] += v1x; s_sq[ni][0] += v1x * v1x;
                s_sum[ni][1] += v1y; s_sq[ni][1] += v1y * v1y;
            }
        }
    }
    // reduce across the 8 lane-groups (lanes differing in bits 2..4)
#pragma unroll
    for (int ni = 0; ni < 4; ni++)
#pragma unroll
        for (int b = 0; b < 2; b++) {
            float s = s_sum[ni][b], q = s_sq[ni][b];
#pragma unroll
            for (int off = 4; off < 32; off <<= 1) {
                s += __shfl_xor_sync(0xffffffffu, s, off);
                q += __shfl_xor_sync(0xffffffffu, q, off);
            }
            if (grp == 0) {
                int c = n0 + wcol0 + ni * 8 + 2 * tig + b;
                atomicAdd(&g_sum[c], s);
                atomicAdd(&g_sumsq[c], q);
            }
        }
}

// ---------------- BN finalize -----------------------------------------------------
__global__ void k_finalize(int n, const float* __restrict__ gamma,
                           const float* __restrict__ beta) {
    int c = threadIdx.x;
    float invn = 1.f / (float)n;
    float mean = g_sum[c] * invn;
    float var  = g_sumsq[c] * invn - mean * mean;
    float s    = gamma[c] * rsqrtf(var + BN_EPS);
    g_scale[c] = s;
    g_shift[c] = beta[c] - mean * s;
}

// ---------------- max aggregation (BN affine fused, sign-safe, MLP 4) --------------
__global__ void k_maxagg(float* __restrict__ out) {
    int v = blockIdx.x;
    int t = threadIdx.x;
    float4 mx = *reinterpret_cast<const float4*>(g_x + (size_t)v * D + t * 4);
    float4 mn = mx;
    int beg = g_off[v], end = g_off[v + 1];
    int j = beg;
    for (; j + 4 <= end; j += 4) {
        int u0 = g_csr[j], u1 = g_csr[j + 1], u2 = g_csr[j + 2], u3 = g_csr[j + 3];
        float4 w0 = *reinterpret_cast<const float4*>(g_x + (size_t)u0 * D + t * 4);
        float4 w1 = *reinterpret_cast<const float4*>(g_x + (size_t)u1 * D + t * 4);
        float4 w2 = *reinterpret_cast<const float4*>(g_x + (size_t)u2 * D + t * 4);
        float4 w3 = *reinterpret_cast<const float4*>(g_x + (size_t)u3 * D + t * 4);
        float hx = fmaxf(fmaxf(w0.x, w1.x), fmaxf(w2.x, w3.x));
        float lx = fminf(fminf(w0.x, w1.x), fminf(w2.x, w3.x));
        float hy = fmaxf(fmaxf(w0.y, w1.y), fmaxf(w2.y, w3.y));
        float ly = fminf(fminf(w0.y, w1.y), fminf(w2.y, w3.y));
        float hz = fmaxf(fmaxf(w0.z, w1.z), fmaxf(w2.z, w3.z));
        float lz = fminf(fminf(w0.z, w1.z), fminf(w2.z, w3.z));
        float hw = fmaxf(fmaxf(w0.w, w1.w), fmaxf(w2.w, w3.w));
        float lw = fminf(fminf(w0.w, w1.w), fminf(w2.w, w3.w));
        mx.x = fmaxf(mx.x, hx); mn.x = fminf(mn.x, lx);
        mx.y = fmaxf(mx.y, hy); mn.y = fminf(mn.y, ly);
        mx.z = fmaxf(mx.z, hz); mn.z = fminf(mn.z, lz);
        mx.w = fmaxf(mx.w, hw); mn.w = fminf(mn.w, lw);
    }
    for (; j < end; j++) {
        int u = g_csr[j];
        float4 w = *reinterpret_cast<const float4*>(g_x + (size_t)u * D + t * 4);
        mx.x = fmaxf(mx.x, w.x); mn.x = fminf(mn.x, w.x);
        mx.y = fmaxf(mx.y, w.y); mn.y = fminf(mn.y, w.y);
        mx.z = fmaxf(mx.z, w.z); mn.z = fminf(mn.z, w.z);
        mx.w = fmaxf(mx.w, w.w); mn.w = fminf(mn.w, w.w);
    }
    float4 sc = reinterpret_cast<const float4*>(g_scale)[t];
    float4 sh = reinterpret_cast<const float4*>(g_shift)[t];
    float4 r;
    r.x = (sc.x >= 0.f ? mx.x : mn.x) * sc.x + sh.x;
    r.y = (sc.y >= 0.f ? mx.y : mn.y) * sc.y + sh.y;
    r.z = (sc.z >= 0.f ? mx.z : mn.z) * sc.z + sh.z;
    r.w = (sc.w >= 0.f ? mx.w : mn.w) * sc.w + sh.w;
    reinterpret_cast<float4*>(out + (size_t)v * D)[t] = r;
}

// ---------------- launch -------------------------------------------------------------
extern "C" void kernel_launch(void* const* d_in, const int* in_sizes, int n_in,
                              void* d_out, int out_size) {
    const float* feats = (const float*)d_in[0];
    const int*   src   = (const int*)d_in[1];
    const int*   dst   = (const int*)d_in[2];
    const float* Wl    = (const float*)d_in[3];
    const float* Wr    = (const float*)d_in[4];
    const float* bl    = (const float*)d_in[5];
    const float* gamma = (const float*)d_in[6];
    const float* beta  = (const float*)d_in[7];
    float* out = (float*)d_out;

    int n = in_sizes[0] / D;
    int e = in_sizes[1];

    cudaFuncSetAttribute(k_gemm, cudaFuncAttributeMaxDynamicSharedMemorySize,
                         SMEM_BYTES);

    void *p_deg, *p_sum, *p_sumsq, *p_bcur;
    cudaGetSymbolAddress(&p_deg, g_deg);
    cudaGetSymbolAddress(&p_sum, g_sum);
    cudaGetSymbolAddress(&p_sumsq, g_sumsq);
    cudaGetSymbolAddress(&p_bcur, g_bcur);
    cudaMemsetAsync(p_deg, 0, (size_t)n * sizeof(int));
    cudaMemsetAsync(p_sum, 0, D * sizeof(float));
    cudaMemsetAsync(p_sumsq, 0, D * sizeof(float));
    cudaMemsetAsync(p_bcur, 0, NBUK * sizeof(int));

    k_degcount<<<(e + 255) / 256, 256>>>(dst, e);
    k_scan<<<1, 1024>>>(n);
    int e2 = (e + 1) >> 1;
    k_fill<<<(e2 + n + 255) / 256, 256>>>(src, dst, e, n);
    k_nbrsum<<<n, 128>>>(feats);
    k_gemm<<<dim3(D / TN, MAXT), 256, SMEM_BYTES>>>(feats, Wl, Wr, bl);
    k_finalize<<<1, D>>>(n, gamma, beta);
    k_maxagg<<<n, 128>>>(out);
}

// round 8
// speedup vs baseline: 1.0839x; 1.0839x over previous
#include <cuda_runtime.h>
#include <cstdint>

#define NMAX   20000
#define EMAX   160000
#define D      512
#define NBUK   11
#define TM     128
#define MAXT   ((NMAX + TM - 1) / TM + NBUK)   // 168
#define BN_EPS 1e-5f

#define TN  128
#define TK  32
#define APITCH 36    // words; 144B rows, 16B-aligned, conflict-free frag reads
#define BPITCH 136   // words; 544B rows, 16B-aligned, conflict-free frag reads
#define A_WORDS (TM * APITCH)            // 4608
#define B_WORDS (TK * BPITCH)            // 4352
#define STAGES 3
#define STAGE_WORDS (A_WORDS + B_WORDS)  // 8960 words = 35840 B (16B-aligned)
#define SMEM_WORDS (STAGES * STAGE_WORDS)
#define SMEM_BYTES (SMEM_WORDS*4 + TM*4) // buffers + perm_s = 108032 B

// ---------------- scratch (device globals; no allocation allowed) -------------
__device__ int   g_deg[NMAX];
__device__ int   g_off[NMAX + 1];
__device__ int   g_cur[NMAX];
__device__ int   g_csr[EMAX];
__device__ int   g_bcnt[NBUK];
__device__ int   g_boff[NBUK + 1];
__device__ int   g_bcur[NBUK];
__device__ int   g_perm[NMAX];
__device__ int   g_tile_bucket[MAXT];
__device__ int   g_tile_row[MAXT];
__device__ int   g_tile_rows[MAXT];
__device__ int   g_ntiles;
__device__ float g_h[(size_t)NMAX * D];     // neighbor sums
__device__ float g_x[(size_t)NMAX * D];     // pre-BN linear output
__device__ float g_sum[D], g_sumsq[D], g_scale[D], g_shift[D];

// ---------------- helpers -----------------------------------------------------
__device__ __forceinline__ void mma_tf32(float c[4], const uint32_t a[4],
                                         const uint32_t b[2]) {
    asm volatile(
        "mma.sync.aligned.m16n8k8.row.col.f32.tf32.tf32.f32 "
        "{%0,%1,%2,%3}, {%4,%5,%6,%7}, {%8,%9}, {%0,%1,%2,%3};\n"
        : "+f"(c[0]), "+f"(c[1]), "+f"(c[2]), "+f"(c[3])
        : "r"(a[0]), "r"(a[1]), "r"(a[2]), "r"(a[3]), "r"(b[0]), "r"(b[1]));
}

__device__ __forceinline__ void cp_async16(uint32_t saddr, const void* gaddr,
                                           int src_bytes) {
    asm volatile("cp.async.cg.shared.global [%0], [%1], 16, %2;\n"
                 :: "r"(saddr), "l"(gaddr), "r"(src_bytes));
}
__device__ __forceinline__ void cp_commit() {
    asm volatile("cp.async.commit_group;\n");
}
__device__ __forceinline__ void cp_wait1() {
    asm volatile("cp.async.wait_group 1;\n");
}

// ---------------- setup kernels ------------------------------------------------
__global__ void k_zero(int n) {
    int i = blockIdx.x * blockDim.x + threadIdx.x;
    if (i < n) g_deg[i] = 0;
    if (i < D) { g_sum[i] = 0.f; g_sumsq[i] = 0.f; }
    if (i < NBUK) { g_bcnt[i] = 0; g_bcur[i] = 0; }
}

__global__ void k_degcount(const int* __restrict__ dst, int e) {
    int i = blockIdx.x * blockDim.x + threadIdx.x;
    if (i < e) atomicAdd(&g_deg[dst[i]], 1);
}

// scan (warp-shuffle based) + bucket histogram + tile map, one block
__global__ void k_scan(int n) {
    __shared__ int wsum[32];
    __shared__ int bc[NBUK];
    int t = threadIdx.x, lane = t & 31, w = t >> 5;
    if (t < NBUK) bc[t] = 0;
    int carry = 0;
    int nchunk = (n + 1023) >> 10;
    for (int ch = 0; ch < nchunk; ch++) {
        int i = ch * 1024 + t;
        int v = (i < n) ? g_deg[i] : 0;
        int x = v;
#pragma unroll
        for (int o = 1; o < 32; o <<= 1) {
            int y = __shfl_up_sync(0xffffffffu, x, o);
            if (lane >= o) x += y;
        }
        if (lane == 31) wsum[w] = x;
        __syncthreads();
        if (w == 0) {
            int s = wsum[lane];
#pragma unroll
            for (int o = 1; o < 32; o <<= 1) {
                int y = __shfl_up_sync(0xffffffffu, s, o);
                if (lane >= o) s += y;
            }
            wsum[lane] = s;
        }
        __syncthreads();
        int prev = (w > 0) ? wsum[w - 1] : 0;
        if (i < n) {
            int ex = carry + prev + x - v;
            g_off[i] = ex;
            g_cur[i] = ex;
        }
        carry += wsum[31];
        __syncthreads();
    }
    if (t == 0) g_off[n] = carry;
    for (int i = t; i < n; i += 1024) {
        int dd = g_deg[i];
        if (dd > NBUK - 1) dd = NBUK - 1;
        atomicAdd(&bc[dd], 1);
    }
    __syncthreads();
    if (t == 0) {
        int acc = 0;
        for (int dd = 0; dd < NBUK; dd++) {
            g_bcnt[dd] = bc[dd];
            g_boff[dd] = acc;
            acc += bc[dd];
        }
        g_boff[NBUK] = acc;
        int tt = 0;
        for (int dd = 0; dd < NBUK; dd++) {
            int c = bc[dd], o = g_boff[dd];
            for (int r = 0; r < c; r += TM) {
                g_tile_bucket[tt] = dd;
                g_tile_row[tt]    = o + r;
                g_tile_rows[tt]   = (c - r < TM) ? (c - r) : TM;
                tt++;
            }
        }
        g_ntiles = tt;
    }
}

// CSR fill + bucket fill (merged)
__global__ void k_fill(const int* __restrict__ src, const int* __restrict__ dst,
                       int e, int n) {
    int i = blockIdx.x * blockDim.x + threadIdx.x;
    if (i < e) {
        int pos = atomicAdd(&g_cur[dst[i]], 1);
        g_csr[pos] = src[i];
    }
    int v = i - e;
    if (v >= 0 && v < n) {
        int dd = g_deg[v];
        if (dd > NBUK - 1) dd = NBUK - 1;
        int pos = g_boff[dd] + atomicAdd(&g_bcur[dd], 1);
        g_perm[pos] = v;
    }
}

// ---------------- neighbor sum (MLP 4) --------------------------------------------
__global__ void k_nbrsum(const float* __restrict__ feats) {
    int v = blockIdx.x;
    int t = threadIdx.x;
    float4 acc = make_float4(0.f, 0.f, 0.f, 0.f);
    int beg = g_off[v], end = g_off[v + 1];
    int j = beg;
    for (; j + 4 <= end; j += 4) {
        int u0 = g_csr[j], u1 = g_csr[j + 1], u2 = g_csr[j + 2], u3 = g_csr[j + 3];
        float4 w0 = *reinterpret_cast<const float4*>(feats + (size_t)u0 * D + t * 4);
        float4 w1 = *reinterpret_cast<const float4*>(feats + (size_t)u1 * D + t * 4);
        float4 w2 = *reinterpret_cast<const float4*>(feats + (size_t)u2 * D + t * 4);
        float4 w3 = *reinterpret_cast<const float4*>(feats + (size_t)u3 * D + t * 4);
        acc.x += (w0.x + w1.x) + (w2.x + w3.x);
        acc.y += (w0.y + w1.y) + (w2.y + w3.y);
        acc.z += (w0.z + w1.z) + (w2.z + w3.z);
        acc.w += (w0.w + w1.w) + (w2.w + w3.w);
    }
    for (; j < end; j++) {
        int u = g_csr[j];
        float4 w = *reinterpret_cast<const float4*>(feats + (size_t)u * D + t * 4);
        acc.x += w.x; acc.y += w.y; acc.z += w.z; acc.w += w.w;
    }
    *reinterpret_cast<float4*>(g_h + (size_t)v * D + t * 4) = acc;
}

// ---------------- bucketed tf32 GEMM, 3-stage cp.async, occ 2 --------------------
// x[node] = [h|feats](K=1024) @ [Wl[d];Wr[d]](1024x512) + bl[d]; BN stats fused.
__global__ __launch_bounds__(256, 2)
void k_gemm(const float* __restrict__ feats, const float* __restrict__ Wl,
            const float* __restrict__ Wr, const float* __restrict__ bl) {
    int tileId = blockIdx.y;
    if (tileId >= g_ntiles) return;
    int d     = g_tile_bucket[tileId];
    int row0  = g_tile_row[tileId];
    int nrows = g_tile_rows[tileId];
    int n0    = blockIdx.x * TN;

    extern __shared__ float smem[];
    int* perm_s = (int*)(smem + SMEM_WORDS);

    int tid  = threadIdx.x;
    int lane = tid & 31;
    int warp = tid >> 5;
    int grp  = lane >> 2;
    int tig  = lane & 3;
    int wrow0 = (warp & 1) * 64;
    int wcol0 = (warp >> 1) * 32;

    if (tid < TM) perm_s[tid] = (tid < nrows) ? g_perm[row0 + tid] : -1;
    __syncthreads();

    // per-thread load coordinates
    int a_row = tid >> 3, a_f4 = tid & 7;     // + p*32 rows
    int b_kr  = tid >> 5, b_f4 = tid & 31;    // + p*8 k-rows

    uint32_t a_s[4], b_s[4];
    size_t a_goff[4];                          // ELEMENT offsets into g_h/feats
    int a_valid[4];
#pragma unroll
    for (int p = 0; p < 4; p++) {
        int row = a_row + p * 32;
        int node = perm_s[row];
        a_valid[p] = (node >= 0) ? 16 : 0;
        if (node < 0) node = 0;
        a_goff[p] = (size_t)node * D + (size_t)(a_f4 * 4);
        a_s[p] = (uint32_t)__cvta_generic_to_shared(
            &smem[row * APITCH + a_f4 * 4]);
        b_s[p] = (uint32_t)__cvta_generic_to_shared(
            &smem[A_WORDS + (b_kr + p * 8) * BPITCH + b_f4 * 4]);
    }
    const size_t wbase = (size_t)d * D * D + (size_t)n0;

    auto load_stage = [&](int kk, int stg) {
        const float* aptr = (kk < 512) ? g_h : feats;
        const float* wptr = (kk < 512) ? Wl : Wr;
        int kb = kk & 511;
        uint32_t soff = (uint32_t)(stg * (STAGE_WORDS * 4));
#pragma unroll
        for (int p = 0; p < 4; p++)
            cp_async16(a_s[p] + soff, aptr + a_goff[p] + kb, a_valid[p]);
#pragma unroll
        for (int p = 0; p < 4; p++)
            cp_async16(b_s[p] + soff,
                       wptr + wbase + (size_t)(kb + b_kr + p * 8) * D + b_f4 * 4, 16);
    };

    float acc[4][4][4];
#pragma unroll
    for (int mi = 0; mi < 4; mi++)
#pragma unroll
        for (int ni = 0; ni < 4; ni++)
#pragma unroll
            for (int q = 0; q < 4; q++) acc[mi][ni][q] = 0.f;

    load_stage(0, 0); cp_commit();
    load_stage(TK, 1); cp_commit();

    int stage = 0;
#pragma unroll 1
    for (int kt = 0; kt < 1024 / TK; kt++) {
        cp_wait1();
        __syncthreads();
        // prefetch stage kt+2 into the buffer last read at iteration kt-1
        if (kt + 2 < 1024 / TK) {
            int nstg = stage + 2; if (nstg >= STAGES) nstg -= STAGES;
            load_stage((kt + 2) * TK, nstg);
        }
        cp_commit();

        const uint32_t* As = (const uint32_t*)(smem + stage * STAGE_WORDS);
        const uint32_t* Bs = As + A_WORDS;
#pragma unroll
        for (int k8 = 0; k8 < TK; k8 += 8) {
            uint32_t af[4][4], bf[4][2];
#pragma unroll
            for (int mi = 0; mi < 4; mi++) {
                int r0 = wrow0 + mi * 16 + grp;
                af[mi][0] = As[r0 * APITCH + k8 + tig];
                af[mi][1] = As[(r0 + 8) * APITCH + k8 + tig];
                af[mi][2] = As[r0 * APITCH + k8 + tig + 4];
                af[mi][3] = As[(r0 + 8) * APITCH + k8 + tig + 4];
            }
#pragma unroll
            for (int ni = 0; ni < 4; ni++) {
                int c0 = wcol0 + ni * 8 + grp;
                bf[ni][0] = Bs[(k8 + tig) * BPITCH + c0];
                bf[ni][1] = Bs[(k8 + tig + 4) * BPITCH + c0];
            }
#pragma unroll
            for (int mi = 0; mi < 4; mi++)
#pragma unroll
                for (int ni = 0; ni < 4; ni++)
                    mma_tf32(acc[mi][ni], af[mi], bf[ni]);
        }
        stage = stage + 1; if (stage >= STAGES) stage = 0;
    }

    // epilogue: bias add, store, fused BN column sums
    float2 bias[4];
#pragma unroll
    for (int ni = 0; ni < 4; ni++)
        bias[ni] = *reinterpret_cast<const float2*>(
            bl + (size_t)d * D + n0 + wcol0 + ni * 8 + 2 * tig);

    float s_sum[4][2] = {}, s_sq[4][2] = {};
#pragma unroll
    for (int mi = 0; mi < 4; mi++) {
        int r0 = wrow0 + mi * 16 + grp;
        int node0 = perm_s[r0];
        int node1 = perm_s[r0 + 8];
#pragma unroll
        for (int ni = 0; ni < 4; ni++) {
            int cc = wcol0 + ni * 8 + 2 * tig;
            float v0x = acc[mi][ni][0] + bias[ni].x;
            float v0y = acc[mi][ni][1] + bias[ni].y;
            float v1x = acc[mi][ni][2] + bias[ni].x;
            float v1y = acc[mi][ni][3] + bias[ni].y;
            if (node0 >= 0) {
                float2 v; v.x = v0x; v.y = v0y;
                *reinterpret_cast<float2*>(g_x + (size_t)node0 * D + n0 + cc) = v;
                s_sum[ni][0] += v0x; s_sq[ni][0] += v0x * v0x;
                s_sum[ni][1] += v0y; s_sq[ni][1] += v0y * v0y;
            }
            if (node1 >= 0) {
                float2 v; v.x = v1x; v.y = v1y;
                *reinterpret_cast<float2*>(g_x + (size_t)node1 * D + n0 + cc) = v;
                s_sum[ni][0] += v1x; s_sq[ni][0] += v1x * v1x;
                s_sum[ni][1] += v1y; s_sq[ni][1] += v1y * v1y;
            }
        }
    }
    // reduce across the 8 lane-groups (lanes differing in bits 2..4)
#pragma unroll
    for (int ni = 0; ni < 4; ni++)
#pragma unroll
        for (int b = 0; b < 2; b++) {
            float s = s_sum[ni][b], q = s_sq[ni][b];
#pragma unroll
            for (int off = 4; off < 32; off <<= 1) {
                s += __shfl_xor_sync(0xffffffffu, s, off);
                q += __shfl_xor_sync(0xffffffffu, q, off);
            }
            if (grp == 0) {
                int c = n0 + wcol0 + ni * 8 + 2 * tig + b;
                atomicAdd(&g_sum[c], s);
                atomicAdd(&g_sumsq[c], q);
            }
        }
}

// ---------------- BN finalize -----------------------------------------------------
__global__ void k_finalize(int n, const float* __restrict__ gamma,
                           const float* __restrict__ beta) {
    int c = threadIdx.x;
    float invn = 1.f / (float)n;
    float mean = g_sum[c] * invn;
    float var  = g_sumsq[c] * invn - mean * mean;
    float s    = gamma[c] * rsqrtf(var + BN_EPS);
    g_scale[c] = s;
    g_shift[c] = beta[c] - mean * s;
}

// ---------------- max aggregation (BN affine fused, sign-safe, MLP 4) --------------
__global__ void k_maxagg(float* __restrict__ out) {
    int v = blockIdx.x;
    int t = threadIdx.x;
    float4 mx = *reinterpret_cast<const float4*>(g_x + (size_t)v * D + t * 4);
    float4 mn = mx;
    int beg = g_off[v], end = g_off[v + 1];
    int j = beg;
    for (; j + 4 <= end; j += 4) {
        int u0 = g_csr[j], u1 = g_csr[j + 1], u2 = g_csr[j + 2], u3 = g_csr[j + 3];
        float4 w0 = *reinterpret_cast<const float4*>(g_x + (size_t)u0 * D + t * 4);
        float4 w1 = *reinterpret_cast<const float4*>(g_x + (size_t)u1 * D + t * 4);
        float4 w2 = *reinterpret_cast<const float4*>(g_x + (size_t)u2 * D + t * 4);
        float4 w3 = *reinterpret_cast<const float4*>(g_x + (size_t)u3 * D + t * 4);
        float hx = fmaxf(fmaxf(w0.x, w1.x), fmaxf(w2.x, w3.x));
        float lx = fminf(fminf(w0.x, w1.x), fminf(w2.x, w3.x));
        float hy = fmaxf(fmaxf(w0.y, w1.y), fmaxf(w2.y, w3.y));
        float ly = fminf(fminf(w0.y, w1.y), fminf(w2.y, w3.y));
        float hz = fmaxf(fmaxf(w0.z, w1.z), fmaxf(w2.z, w3.z));
        float lz = fminf(fminf(w0.z, w1.z), fminf(w2.z, w3.z));
        float hw = fmaxf(fmaxf(w0.w, w1.w), fmaxf(w2.w, w3.w));
        float lw = fminf(fminf(w0.w, w1.w), fminf(w2.w, w3.w));
        mx.x = fmaxf(mx.x, hx); mn.x = fminf(mn.x, lx);
        mx.y = fmaxf(mx.y, hy); mn.y = fminf(mn.y, ly);
        mx.z = fmaxf(mx.z, hz); mn.z = fminf(mn.z, lz);
        mx.w = fmaxf(mx.w, hw); mn.w = fminf(mn.w, lw);
    }
    for (; j < end; j++) {
        int u = g_csr[j];
        float4 w = *reinterpret_cast<const float4*>(g_x + (size_t)u * D + t * 4);
        mx.x = fmaxf(mx.x, w.x); mn.x = fminf(mn.x, w.x);
        mx.y = fmaxf(mx.y, w.y); mn.y = fminf(mn.y, w.y);
        mx.z = fmaxf(mx.z, w.z); mn.z = fminf(mn.z, w.z);
        mx.w = fmaxf(mx.w, w.w); mn.w = fminf(mn.w, w.w);
    }
    float4 sc = reinterpret_cast<const float4*>(g_scale)[t];
    float4 sh = reinterpret_cast<const float4*>(g_shift)[t];
    float4 r;
    r.x = (sc.x >= 0.f ? mx.x : mn.x) * sc.x + sh.x;
    r.y = (sc.y >= 0.f ? mx.y : mn.y) * sc.y + sh.y;
    r.z = (sc.z >= 0.f ? mx.z : mn.z) * sc.z + sh.z;
    r.w = (sc.w >= 0.f ? mx.w : mn.w) * sc.w + sh.w;
    reinterpret_cast<float4*>(out + (size_t)v * D)[t] = r;
}

// ---------------- launch -------------------------------------------------------------
extern "C" void kernel_launch(void* const* d_in, const int* in_sizes, int n_in,
                              void* d_out, int out_size) {
    const float* feats = (const float*)d_in[0];
    const int*   src   = (const int*)d_in[1];
    const int*   dst   = (const int*)d_in[2];
    const float* Wl    = (const float*)d_in[3];
    const float* Wr    = (const float*)d_in[4];
    const float* bl    = (const float*)d_in[5];
    const float* gamma = (const float*)d_in[6];
    const float* beta  = (const float*)d_in[7];
    float* out = (float*)d_out;

    int n = in_sizes[0] / D;
    int e = in_sizes[1];

    cudaFuncSetAttribute(k_gemm, cudaFuncAttributeMaxDynamicSharedMemorySize,
                         SMEM_BYTES);

    k_zero<<<(n + 255) / 256, 256>>>(n);
    k_degcount<<<(e + 255) / 256, 256>>>(dst, e);
    k_scan<<<1, 1024>>>(n);
    k_fill<<<(e + n + 255) / 256, 256>>>(src, dst, e, n);
    k_nbrsum<<<n, 128>>>(feats);
    k_gemm<<<dim3(D / TN, MAXT), 256, SMEM_BYTES>>>(feats, Wl, Wr, bl);
    k_finalize<<<1, D>>>(n, gamma, beta);
    k_maxagg<<<n, 128>>>(out);
}

// round 9
// speedup vs baseline: 1.3598x; 1.2545x over previous
#include <cuda_runtime.h>
#include <cuda_fp16.h>
#include <cstdint>

#define NMAX   20000
#define EMAX   160000
#define D      512
#define KTOT   1024
#define NBUK   11
#define TM     128
#define MAXT   ((NMAX + TM - 1) / TM + NBUK)   // 168
#define BN_EPS 1e-5f

#define TN  128
#define TK  64      // halfs of K per stage
#define PITCH 36    // words per 64-half row (128B data + 16B pad): conflict-free
#define A_WORDS (TM * PITCH)             // 4608
#define B_WORDS (TN * PITCH)             // 4608
#define STAGES 3
#define STAGE_WORDS (A_WORDS + B_WORDS)  // 9216 words = 36864 B
#define SMEM_WORDS (STAGES * STAGE_WORDS)
#define SMEM_BYTES (SMEM_WORDS*4 + TM*4) // + perm_s = 111104 B (2 CTAs/SM fit)

// ---------------- scratch (device globals; no allocation allowed) -------------
__device__ int    g_deg[NMAX];
__device__ int    g_off[NMAX + 1];
__device__ int    g_cur[NMAX];
__device__ int    g_csr[EMAX];
__device__ int    g_bcnt[NBUK];
__device__ int    g_boff[NBUK + 1];
__device__ int    g_bcur[NBUK];
__device__ int    g_perm[NMAX];
__device__ int    g_tile_bucket[MAXT];
__device__ int    g_tile_row[MAXT];
__device__ int    g_tile_rows[MAXT];
__device__ int    g_ntiles;
__device__ __half g_hh[(size_t)NMAX * D];        // neighbor sums (fp16)
__device__ __half g_featsh[(size_t)NMAX * D];    // feats (fp16)
__device__ __half g_wth[(size_t)NBUK * D * KTOT];// packed fp16 weights [d][n][k]
__device__ float  g_x[(size_t)NMAX * D];         // pre-BN linear output
__device__ float  g_sum[D], g_sumsq[D], g_scale[D], g_shift[D];

// ---------------- helpers -----------------------------------------------------
__device__ __forceinline__ void mma_f16(float c[4], const uint32_t a[4],
                                        const uint32_t b[2]) {
    asm volatile(
        "mma.sync.aligned.m16n8k16.row.col.f32.f16.f16.f32 "
        "{%0,%1,%2,%3}, {%4,%5,%6,%7}, {%8,%9}, {%0,%1,%2,%3};\n"
        : "+f"(c[0]), "+f"(c[1]), "+f"(c[2]), "+f"(c[3])
        : "r"(a[0]), "r"(a[1]), "r"(a[2]), "r"(a[3]), "r"(b[0]), "r"(b[1]));
}

__device__ __forceinline__ void cp_async16(uint32_t saddr, const void* gaddr,
                                           int src_bytes) {
    asm volatile("cp.async.cg.shared.global [%0], [%1], 16, %2;\n"
                 :: "r"(saddr), "l"(gaddr), "r"(src_bytes));
}
__device__ __forceinline__ void cp_commit() {
    asm volatile("cp.async.commit_group;\n");
}
__device__ __forceinline__ void cp_wait1() {
    asm volatile("cp.async.wait_group 1;\n");
}

// ---------------- setup kernels ------------------------------------------------
__global__ void k_zero(int n) {
    int i = blockIdx.x * blockDim.x + threadIdx.x;
    if (i < n) g_deg[i] = 0;
    if (i < D) { g_sum[i] = 0.f; g_sumsq[i] = 0.f; }
    if (i < NBUK) { g_bcnt[i] = 0; g_bcur[i] = 0; }
}

// weights fp32 [d][k][n] -> fp16 [d][n][k] (transposed)
__global__ void k_prepack(const float* __restrict__ Wl,
                          const float* __restrict__ Wr) {
    __shared__ float s[32][33];
    int d  = blockIdx.z;
    int nt = blockIdx.x * 32;
    int kt = blockIdx.y * 32;     // 0..1023
    int tx = threadIdx.x, ty = threadIdx.y;
    const float* Wsrc = (kt < 512) ? Wl : Wr;
    int kb = kt & 511;
#pragma unroll
    for (int i = 0; i < 4; i++)
        s[ty + i * 8][tx] = Wsrc[((size_t)d * 512 + kb + ty + i * 8) * D + nt + tx];
    __syncthreads();
#pragma unroll
    for (int i = 0; i < 4; i++) {
        int nn = nt + ty + i * 8;
        g_wth[((size_t)d * D + nn) * KTOT + kt + tx] = __float2half(s[tx][ty + i * 8]);
    }
}

// feats fp32 -> fp16
__global__ void k_cvt(const float* __restrict__ feats, int total4) {
    int i = blockIdx.x * blockDim.x + threadIdx.x;
    if (i < total4) {
        float4 f = reinterpret_cast<const float4*>(feats)[i];
        __half2 h0 = __floats2half2_rn(f.x, f.y);
        __half2 h1 = __floats2half2_rn(f.z, f.w);
        reinterpret_cast<__half2*>(g_featsh)[i * 2]     = h0;
        reinterpret_cast<__half2*>(g_featsh)[i * 2 + 1] = h1;
    }
}

__global__ void k_degcount(const int* __restrict__ dst, int e) {
    int i = blockIdx.x * blockDim.x + threadIdx.x;
    if (i < e) atomicAdd(&g_deg[dst[i]], 1);
}

// scan (warp-shuffle based) + bucket histogram + tile map, one block
__global__ void k_scan(int n) {
    __shared__ int wsum[32];
    __shared__ int bc[NBUK];
    int t = threadIdx.x, lane = t & 31, w = t >> 5;
    if (t < NBUK) bc[t] = 0;
    int carry = 0;
    int nchunk = (n + 1023) >> 10;
    for (int ch = 0; ch < nchunk; ch++) {
        int i = ch * 1024 + t;
        int v = (i < n) ? g_deg[i] : 0;
        int x = v;
#pragma unroll
        for (int o = 1; o < 32; o <<= 1) {
            int y = __shfl_up_sync(0xffffffffu, x, o);
            if (lane >= o) x += y;
        }
        if (lane == 31) wsum[w] = x;
        __syncthreads();
        if (w == 0) {
            int s = wsum[lane];
#pragma unroll
            for (int o = 1; o < 32; o <<= 1) {
                int y = __shfl_up_sync(0xffffffffu, s, o);
                if (lane >= o) s += y;
            }
            wsum[lane] = s;
        }
        __syncthreads();
        int prev = (w > 0) ? wsum[w - 1] : 0;
        if (i < n) {
            int ex = carry + prev + x - v;
            g_off[i] = ex;
            g_cur[i] = ex;
        }
        carry += wsum[31];
        __syncthreads();
    }
    if (t == 0) g_off[n] = carry;
    for (int i = t; i < n; i += 1024) {
        int dd = g_deg[i];
        if (dd > NBUK - 1) dd = NBUK - 1;
        atomicAdd(&bc[dd], 1);
    }
    __syncthreads();
    if (t == 0) {
        int acc = 0;
        for (int dd = 0; dd < NBUK; dd++) {
            g_bcnt[dd] = bc[dd];
            g_boff[dd] = acc;
            acc += bc[dd];
        }
        g_boff[NBUK] = acc;
        int tt = 0;
        for (int dd = 0; dd < NBUK; dd++) {
            int c = bc[dd], o = g_boff[dd];
            for (int r = 0; r < c; r += TM) {
                g_tile_bucket[tt] = dd;
                g_tile_row[tt]    = o + r;
                g_tile_rows[tt]   = (c - r < TM) ? (c - r) : TM;
                tt++;
            }
        }
        g_ntiles = tt;
    }
}

// CSR fill + bucket fill (merged)
__global__ void k_fill(const int* __restrict__ src, const int* __restrict__ dst,
                       int e, int n) {
    int i = blockIdx.x * blockDim.x + threadIdx.x;
    if (i < e) {
        int pos = atomicAdd(&g_cur[dst[i]], 1);
        g_csr[pos] = src[i];
    }
    int v = i - e;
    if (v >= 0 && v < n) {
        int dd = g_deg[v];
        if (dd > NBUK - 1) dd = NBUK - 1;
        int pos = g_boff[dd] + atomicAdd(&g_bcur[dd], 1);
        g_perm[pos] = v;
    }
}

// ---------------- neighbor sum (fp32 acc, fp16 out) --------------------------------
__global__ void k_nbrsum(const float* __restrict__ feats) {
    int v = blockIdx.x;
    int t = threadIdx.x;
    float4 acc = make_float4(0.f, 0.f, 0.f, 0.f);
    int beg = g_off[v], end = g_off[v + 1];
    int j = beg;
    for (; j + 4 <= end; j += 4) {
        int u0 = g_csr[j], u1 = g_csr[j + 1], u2 = g_csr[j + 2], u3 = g_csr[j + 3];
        float4 w0 = *reinterpret_cast<const float4*>(feats + (size_t)u0 * D + t * 4);
        float4 w1 = *reinterpret_cast<const float4*>(feats + (size_t)u1 * D + t * 4);
        float4 w2 = *reinterpret_cast<const float4*>(feats + (size_t)u2 * D + t * 4);
        float4 w3 = *reinterpret_cast<const float4*>(feats + (size_t)u3 * D + t * 4);
        acc.x += (w0.x + w1.x) + (w2.x + w3.x);
        acc.y += (w0.y + w1.y) + (w2.y + w3.y);
        acc.z += (w0.z + w1.z) + (w2.z + w3.z);
        acc.w += (w0.w + w1.w) + (w2.w + w3.w);
    }
    for (; j < end; j++) {
        int u = g_csr[j];
        float4 w = *reinterpret_cast<const float4*>(feats + (size_t)u * D + t * 4);
        acc.x += w.x; acc.y += w.y; acc.z += w.z; acc.w += w.w;
    }
    __half2 h0 = __floats2half2_rn(acc.x, acc.y);
    __half2 h1 = __floats2half2_rn(acc.z, acc.w);
    __half2* dstp = reinterpret_cast<__half2*>(g_hh + (size_t)v * D + t * 4);
    dstp[0] = h0;
    dstp[1] = h1;
}

// ---------------- bucketed fp16 GEMM, 3-stage cp.async, occ 2 --------------------
// x[node] = [h|feats](K=1024,fp16) @ Wt[d](fp16,[n][k]) + bl[d]; BN stats fused.
__global__ __launch_bounds__(256, 2)
void k_gemm(const float* __restrict__ bl) {
    int tileId = blockIdx.y;
    if (tileId >= g_ntiles) return;
    int d     = g_tile_bucket[tileId];
    int row0  = g_tile_row[tileId];
    int nrows = g_tile_rows[tileId];
    int n0    = blockIdx.x * TN;

    extern __shared__ float smem[];
    int* perm_s = (int*)(smem + SMEM_WORDS);

    int tid  = threadIdx.x;
    int lane = tid & 31;
    int warp = tid >> 5;
    int grp  = lane >> 2;
    int tig  = lane & 3;
    int wrow0 = (warp & 1) * 64;
    int wcol0 = (warp >> 1) * 32;

    if (tid < TM) perm_s[tid] = (tid < nrows) ? g_perm[row0 + tid] : -1;
    __syncthreads();

    // per-thread load coordinates: 1024 chunks each for A and B (4/thread each)
    uint32_t a_s[4], b_s[4];
    size_t a_goff[4], b_goff[4];   // HALF-element offsets
    int a_valid[4];
#pragma unroll
    for (int p = 0; p < 4; p++) {
        int c = tid + p * 256;
        int row = c >> 3, ch = c & 7;      // 8 x 16B chunks per 64-half row
        int node = perm_s[row];
        a_valid[p] = (node >= 0) ? 16 : 0;
        if (node < 0) node = 0;
        a_goff[p] = (size_t)node * D + (size_t)(ch * 8);
        a_s[p] = (uint32_t)__cvta_generic_to_shared(
            &smem[row * PITCH + ch * 4]);
        b_goff[p] = ((size_t)d * D + (size_t)(n0 + row)) * KTOT + (size_t)(ch * 8);
        b_s[p] = (uint32_t)__cvta_generic_to_shared(
            &smem[A_WORDS + row * PITCH + ch * 4]);
    }

    auto load_stage = [&](int kk, int stg) {
        const __half* aptr = (kk < 512) ? g_hh : g_featsh;
        int kb = kk & 511;
        uint32_t soff = (uint32_t)(stg * (STAGE_WORDS * 4));
#pragma unroll
        for (int p = 0; p < 4; p++)
            cp_async16(a_s[p] + soff, aptr + a_goff[p] + kb, a_valid[p]);
#pragma unroll
        for (int p = 0; p < 4; p++)
            cp_async16(b_s[p] + soff, g_wth + b_goff[p] + kk, 16);
    };

    float acc[4][4][4];
#pragma unroll
    for (int mi = 0; mi < 4; mi++)
#pragma unroll
        for (int ni = 0; ni < 4; ni++)
#pragma unroll
            for (int q = 0; q < 4; q++) acc[mi][ni][q] = 0.f;

    load_stage(0, 0); cp_commit();
    load_stage(TK, 1); cp_commit();

    const int NIT = KTOT / TK;   // 16
    int stage = 0;
#pragma unroll 1
    for (int kt = 0; kt < NIT; kt++) {
        cp_wait1();
        __syncthreads();
        if (kt + 2 < NIT) {
            int nstg = stage + 2; if (nstg >= STAGES) nstg -= STAGES;
            load_stage((kt + 2) * TK, nstg);
        }
        cp_commit();

        const uint32_t* As = (const uint32_t*)(smem + stage * STAGE_WORDS);
        const uint32_t* Bs = As + A_WORDS;
#pragma unroll
        for (int s16 = 0; s16 < 4; s16++) {       // 4 k16 steps per 64-half stage
            uint32_t af[4][4], bf[4][2];
#pragma unroll
            for (int mi = 0; mi < 4; mi++) {
                int r0 = wrow0 + mi * 16 + grp;
                int base = r0 * PITCH + s16 * 8 + tig;
                af[mi][0] = As[base];
                af[mi][1] = As[base + 8 * PITCH];
                af[mi][2] = As[base + 4];
                af[mi][3] = As[base + 8 * PITCH + 4];
            }
#pragma unroll
            for (int ni = 0; ni < 4; ni++) {
                int nb = (wcol0 + ni * 8 + grp) * PITCH + s16 * 8 + tig;
                bf[ni][0] = Bs[nb];
                bf[ni][1] = Bs[nb + 4];
            }
#pragma unroll
            for (int mi = 0; mi < 4; mi++)
#pragma unroll
                for (int ni = 0; ni < 4; ni++)
                    mma_f16(acc[mi][ni], af[mi], bf[ni]);
        }
        stage = stage + 1; if (stage >= STAGES) stage = 0;
    }

    // epilogue: bias add, store, fused BN column sums
    float2 bias[4];
#pragma unroll
    for (int ni = 0; ni < 4; ni++)
        bias[ni] = *reinterpret_cast<const float2*>(
            bl + (size_t)d * D + n0 + wcol0 + ni * 8 + 2 * tig);

    float s_sum[4][2] = {}, s_sq[4][2] = {};
#pragma unroll
    for (int mi = 0; mi < 4; mi++) {
        int r0 = wrow0 + mi * 16 + grp;
        int node0 = perm_s[r0];
        int node1 = perm_s[r0 + 8];
#pragma unroll
        for (int ni = 0; ni < 4; ni++) {
            int cc = wcol0 + ni * 8 + 2 * tig;
            float v0x = acc[mi][ni][0] + bias[ni].x;
            float v0y = acc[mi][ni][1] + bias[ni].y;
            float v1x = acc[mi][ni][2] + bias[ni].x;
            float v1y = acc[mi][ni][3] + bias[ni].y;
            if (node0 >= 0) {
                float2 v; v.x = v0x; v.y = v0y;
                *reinterpret_cast<float2*>(g_x + (size_t)node0 * D + n0 + cc) = v;
                s_sum[ni][0] += v0x; s_sq[ni][0] += v0x * v0x;
                s_sum[ni][1] += v0y; s_sq[ni][1] += v0y * v0y;
            }
            if (node1 >= 0) {
                float2 v; v.x = v1x; v.y = v1y;
                *reinterpret_cast<float2*>(g_x + (size_t)node1 * D + n0 + cc) = v;
                s_sum[ni][0] += v1x; s_sq[ni][0] += v1x * v1x;
                s_sum[ni][1] += v1y; s_sq[ni][1] += v1y * v1y;
            }
        }
    }
#pragma unroll
    for (int ni = 0; ni < 4; ni++)
#pragma unroll
        for (int b = 0; b < 2; b++) {
            float s = s_sum[ni][b], q = s_sq[ni][b];
#pragma unroll
            for (int off = 4; off < 32; off <<= 1) {
                s += __shfl_xor_sync(0xffffffffu, s, off);
                q += __shfl_xor_sync(0xffffffffu, q, off);
            }
            if (grp == 0) {
                int c = n0 + wcol0 + ni * 8 + 2 * tig + b;
                atomicAdd(&g_sum[c], s);
                atomicAdd(&g_sumsq[c], q);
            }
        }
}

// ---------------- BN finalize -----------------------------------------------------
__global__ void k_finalize(int n, const float* __restrict__ gamma,
                           const float* __restrict__ beta) {
    int c = threadIdx.x;
    float invn = 1.f / (float)n;
    float mean = g_sum[c] * invn;
    float var  = g_sumsq[c] * invn - mean * mean;
    float s    = gamma[c] * rsqrtf(var + BN_EPS);
    g_scale[c] = s;
    g_shift[c] = beta[c] - mean * s;
}

// ---------------- max aggregation (BN affine fused, sign-safe) ---------------------
__global__ void k_maxagg(float* __restrict__ out) {
    int v = blockIdx.x;
    int t = threadIdx.x;
    float4 mx = *reinterpret_cast<const float4*>(g_x + (size_t)v * D + t * 4);
    float4 mn = mx;
    int beg = g_off[v], end = g_off[v + 1];
    int j = beg;
    for (; j + 4 <= end; j += 4) {
        int u0 = g_csr[j], u1 = g_csr[j + 1], u2 = g_csr[j + 2], u3 = g_csr[j + 3];
        float4 w0 = *reinterpret_cast<const float4*>(g_x + (size_t)u0 * D + t * 4);
        float4 w1 = *reinterpret_cast<const float4*>(g_x + (size_t)u1 * D + t * 4);
        float4 w2 = *reinterpret_cast<const float4*>(g_x + (size_t)u2 * D + t * 4);
        float4 w3 = *reinterpret_cast<const float4*>(g_x + (size_t)u3 * D + t * 4);
        float hx = fmaxf(fmaxf(w0.x, w1.x), fmaxf(w2.x, w3.x));
        float lx = fminf(fminf(w0.x, w1.x), fminf(w2.x, w3.x));
        float hy = fmaxf(fmaxf(w0.y, w1.y), fmaxf(w2.y, w3.y));
        float ly = fminf(fminf(w0.y, w1.y), fminf(w2.y, w3.y));
        float hz = fmaxf(fmaxf(w0.z, w1.z), fmaxf(w2.z, w3.z));
        float lz = fminf(fminf(w0.z, w1.z), fminf(w2.z, w3.z));
        float hw = fmaxf(fmaxf(w0.w, w1.w), fmaxf(w2.w, w3.w));
        float lw = fminf(fminf(w0.w, w1.w), fminf(w2.w, w3.w));
        mx.x = fmaxf(mx.x, hx); mn.x = fminf(mn.x, lx);
        mx.y = fmaxf(mx.y, hy); mn.y = fminf(mn.y, ly);
        mx.z = fmaxf(mx.z, hz); mn.z = fminf(mn.z, lz);
        mx.w = fmaxf(mx.w, hw); mn.w = fminf(mn.w, lw);
    }
    for (; j < end; j++) {
        int u = g_csr[j];
        float4 w = *reinterpret_cast<const float4*>(g_x + (size_t)u * D + t * 4);
        mx.x = fmaxf(mx.x, w.x); mn.x = fminf(mn.x, w.x);
        mx.y = fmaxf(mx.y, w.y); mn.y = fminf(mn.y, w.y);
        mx.z = fmaxf(mx.z, w.z); mn.z = fminf(mn.z, w.z);
        mx.w = fmaxf(mx.w, w.w); mn.w = fminf(mn.w, w.w);
    }
    float4 sc = reinterpret_cast<const float4*>(g_scale)[t];
    float4 sh = reinterpret_cast<const float4*>(g_shift)[t];
    float4 r;
    r.x = (sc.x >= 0.f ? mx.x : mn.x) * sc.x + sh.x;
    r.y = (sc.y >= 0.f ? mx.y : mn.y) * sc.y + sh.y;
    r.z = (sc.z >= 0.f ? mx.z : mn.z) * sc.z + sh.z;
    r.w = (sc.w >= 0.f ? mx.w : mn.w) * sc.w + sh.w;
    reinterpret_cast<float4*>(out + (size_t)v * D)[t] = r;
}

// ---------------- launch -------------------------------------------------------------
extern "C" void kernel_launch(void* const* d_in, const int* in_sizes, int n_in,
                              void* d_out, int out_size) {
    const float* feats = (const float*)d_in[0];
    const int*   src   = (const int*)d_in[1];
    const int*   dst   = (const int*)d_in[2];
    const float* Wl    = (const float*)d_in[3];
    const float* Wr    = (const float*)d_in[4];
    const float* bl    = (const float*)d_in[5];
    const float* gamma = (const float*)d_in[6];
    const float* beta  = (const float*)d_in[7];
    float* out = (float*)d_out;

    int n = in_sizes[0] / D;
    int e = in_sizes[1];

    cudaFuncSetAttribute(k_gemm, cudaFuncAttributeMaxDynamicSharedMemorySize,
                         SMEM_BYTES);

    k_zero<<<(n + 255) / 256, 256>>>(n);
    k_prepack<<<dim3(D / 32, KTOT / 32, NBUK), dim3(32, 8)>>>(Wl, Wr);
    k_cvt<<<(n * (D / 4) + 255) / 256, 256>>>(feats, n * (D / 4));
    k_degcount<<<(e + 255) / 256, 256>>>(dst, e);
    k_scan<<<1, 1024>>>(n);
    k_fill<<<(e + n + 255) / 256, 256>>>(src, dst, e, n);
    k_nbrsum<<<n, 128>>>(feats);
    k_gemm<<<dim3(D / TN, MAXT), 256, SMEM_BYTES>>>(bl);
    k_finalize<<<1, D>>>(n, gamma, beta);
    k_maxagg<<<n, 128>>>(out);
}

// round 10
// speedup vs baseline: 1.3979x; 1.0280x over previous
#include <cuda_runtime.h>
#include <cuda_fp16.h>
#include <cstdint>

#define NMAX   20000
#define EMAX   160000
#define D      512
#define KTOT   1024
#define NBUK   11
#define TM     128
#define MAXT   ((NMAX + TM - 1) / TM + NBUK)   // 168
#define BN_EPS 1e-5f

#define TN  128
#define TK  64      // halfs of K per stage
#define PITCH 36    // words per 64-half row (128B data + 16B pad): conflict-free
#define A_WORDS (TM * PITCH)             // 4608
#define B_WORDS (TN * PITCH)             // 4608
#define STAGES 3
#define STAGE_WORDS (A_WORDS + B_WORDS)  // 9216 words = 36864 B
#define SMEM_WORDS (STAGES * STAGE_WORDS)
#define SMEM_BYTES (SMEM_WORDS*4 + TM*4) // + perm_s = 111104 B (2 CTAs/SM fit)

// ---------------- scratch (device globals; no allocation allowed) -------------
__device__ int    g_deg[NMAX];
__device__ int    g_off[NMAX + 1];
__device__ int    g_cur[NMAX];
__device__ int    g_csr[EMAX];
__device__ int    g_bcnt[NBUK];
__device__ int    g_boff[NBUK + 1];
__device__ int    g_bcur[NBUK];
__device__ int    g_perm[NMAX];
__device__ int    g_tile_bucket[MAXT];
__device__ int    g_tile_row[MAXT];
__device__ int    g_tile_rows[MAXT];
__device__ int    g_ntiles;
__device__ __half g_hh[(size_t)NMAX * D];        // neighbor sums (fp16)
__device__ __half g_featsh[(size_t)NMAX * D];    // feats (fp16)
__device__ __half g_wth[(size_t)NBUK * D * KTOT];// packed fp16 weights [d][n][k]
__device__ float  g_x[(size_t)NMAX * D];         // pre-BN linear output
__device__ float  g_sum[D], g_sumsq[D], g_scale[D], g_shift[D];

// ---------------- helpers -----------------------------------------------------
__device__ __forceinline__ void mma_f16(float c[4], const uint32_t a[4],
                                        const uint32_t b[2]) {
    asm volatile(
        "mma.sync.aligned.m16n8k16.row.col.f32.f16.f16.f32 "
        "{%0,%1,%2,%3}, {%4,%5,%6,%7}, {%8,%9}, {%0,%1,%2,%3};\n"
        : "+f"(c[0]), "+f"(c[1]), "+f"(c[2]), "+f"(c[3])
        : "r"(a[0]), "r"(a[1]), "r"(a[2]), "r"(a[3]), "r"(b[0]), "r"(b[1]));
}

__device__ __forceinline__ void ldsm_x4(uint32_t& d0, uint32_t& d1,
                                        uint32_t& d2, uint32_t& d3,
                                        uint32_t saddr) {
    asm volatile("ldmatrix.sync.aligned.m8n8.x4.shared.b16 {%0,%1,%2,%3}, [%4];"
                 : "=r"(d0), "=r"(d1), "=r"(d2), "=r"(d3) : "r"(saddr));
}

__device__ __forceinline__ void cp_async16(uint32_t saddr, const void* gaddr,
                                           int src_bytes) {
    asm volatile("cp.async.cg.shared.global [%0], [%1], 16, %2;\n"
                 :: "r"(saddr), "l"(gaddr), "r"(src_bytes));
}
__device__ __forceinline__ void cp_commit() {
    asm volatile("cp.async.commit_group;\n");
}
__device__ __forceinline__ void cp_wait1() {
    asm volatile("cp.async.wait_group 1;\n");
}

// ---------------- setup kernels ------------------------------------------------
__global__ void k_zero(int n) {
    int i = blockIdx.x * blockDim.x + threadIdx.x;
    if (i < n) g_deg[i] = 0;
    if (i < D) { g_sum[i] = 0.f; g_sumsq[i] = 0.f; }
    if (i < NBUK) { g_bcnt[i] = 0; g_bcur[i] = 0; }
}

// weights fp32 [d][k][n] -> fp16 [d][n][k] (transposed)
__global__ void k_prepack(const float* __restrict__ Wl,
                          const float* __restrict__ Wr) {
    __shared__ float s[32][33];
    int d  = blockIdx.z;
    int nt = blockIdx.x * 32;
    int kt = blockIdx.y * 32;     // 0..1023
    int tx = threadIdx.x, ty = threadIdx.y;
    const float* Wsrc = (kt < 512) ? Wl : Wr;
    int kb = kt & 511;
#pragma unroll
    for (int i = 0; i < 4; i++)
        s[ty + i * 8][tx] = Wsrc[((size_t)d * 512 + kb + ty + i * 8) * D + nt + tx];
    __syncthreads();
#pragma unroll
    for (int i = 0; i < 4; i++) {
        int nn = nt + ty + i * 8;
        g_wth[((size_t)d * D + nn) * KTOT + kt + tx] = __float2half(s[tx][ty + i * 8]);
    }
}

// feats fp32 -> fp16
__global__ void k_cvt(const float* __restrict__ feats, int total4) {
    int i = blockIdx.x * blockDim.x + threadIdx.x;
    if (i < total4) {
        float4 f = reinterpret_cast<const float4*>(feats)[i];
        __half2 h0 = __floats2half2_rn(f.x, f.y);
        __half2 h1 = __floats2half2_rn(f.z, f.w);
        reinterpret_cast<__half2*>(g_featsh)[i * 2]     = h0;
        reinterpret_cast<__half2*>(g_featsh)[i * 2 + 1] = h1;
    }
}

__global__ void k_degcount(const int* __restrict__ dst, int e) {
    int i = blockIdx.x * blockDim.x + threadIdx.x;
    if (i < e) atomicAdd(&g_deg[dst[i]], 1);
}

// scan (warp-shuffle based) + bucket histogram + tile map, one block
__global__ void k_scan(int n) {
    __shared__ int wsum[32];
    __shared__ int bc[NBUK];
    int t = threadIdx.x, lane = t & 31, w = t >> 5;
    if (t < NBUK) bc[t] = 0;
    int carry = 0;
    int nchunk = (n + 1023) >> 10;
    for (int ch = 0; ch < nchunk; ch++) {
        int i = ch * 1024 + t;
        int v = (i < n) ? g_deg[i] : 0;
        int x = v;
#pragma unroll
        for (int o = 1; o < 32; o <<= 1) {
            int y = __shfl_up_sync(0xffffffffu, x, o);
            if (lane >= o) x += y;
        }
        if (lane == 31) wsum[w] = x;
        __syncthreads();
        if (w == 0) {
            int s = wsum[lane];
#pragma unroll
            for (int o = 1; o < 32; o <<= 1) {
                int y = __shfl_up_sync(0xffffffffu, s, o);
                if (lane >= o) s += y;
            }
            wsum[lane] = s;
        }
        __syncthreads();
        int prev = (w > 0) ? wsum[w - 1] : 0;
        if (i < n) {
            int ex = carry + prev + x - v;
            g_off[i] = ex;
            g_cur[i] = ex;
        }
        carry += wsum[31];
        __syncthreads();
    }
    if (t == 0) g_off[n] = carry;
    for (int i = t; i < n; i += 1024) {
        int dd = g_deg[i];
        if (dd > NBUK - 1) dd = NBUK - 1;
        atomicAdd(&bc[dd], 1);
    }
    __syncthreads();
    if (t == 0) {
        int acc = 0;
        for (int dd = 0; dd < NBUK; dd++) {
            g_bcnt[dd] = bc[dd];
            g_boff[dd] = acc;
            acc += bc[dd];
        }
        g_boff[NBUK] = acc;
        int tt = 0;
        for (int dd = 0; dd < NBUK; dd++) {
            int c = bc[dd], o = g_boff[dd];
            for (int r = 0; r < c; r += TM) {
                g_tile_bucket[tt] = dd;
                g_tile_row[tt]    = o + r;
                g_tile_rows[tt]   = (c - r < TM) ? (c - r) : TM;
                tt++;
            }
        }
        g_ntiles = tt;
    }
}

// CSR fill + bucket fill (merged)
__global__ void k_fill(const int* __restrict__ src, const int* __restrict__ dst,
                       int e, int n) {
    int i = blockIdx.x * blockDim.x + threadIdx.x;
    if (i < e) {
        int pos = atomicAdd(&g_cur[dst[i]], 1);
        g_csr[pos] = src[i];
    }
    int v = i - e;
    if (v >= 0 && v < n) {
        int dd = g_deg[v];
        if (dd > NBUK - 1) dd = NBUK - 1;
        int pos = g_boff[dd] + atomicAdd(&g_bcur[dd], 1);
        g_perm[pos] = v;
    }
}

// ---------------- neighbor sum (fp32 acc, fp16 out) --------------------------------
__global__ void k_nbrsum(const float* __restrict__ feats) {
    int v = blockIdx.x;
    int t = threadIdx.x;
    float4 acc = make_float4(0.f, 0.f, 0.f, 0.f);
    int beg = g_off[v], end = g_off[v + 1];
    int j = beg;
    for (; j + 4 <= end; j += 4) {
        int u0 = g_csr[j], u1 = g_csr[j + 1], u2 = g_csr[j + 2], u3 = g_csr[j + 3];
        float4 w0 = *reinterpret_cast<const float4*>(feats + (size_t)u0 * D + t * 4);
        float4 w1 = *reinterpret_cast<const float4*>(feats + (size_t)u1 * D + t * 4);
        float4 w2 = *reinterpret_cast<const float4*>(feats + (size_t)u2 * D + t * 4);
        float4 w3 = *reinterpret_cast<const float4*>(feats + (size_t)u3 * D + t * 4);
        acc.x += (w0.x + w1.x) + (w2.x + w3.x);
        acc.y += (w0.y + w1.y) + (w2.y + w3.y);
        acc.z += (w0.z + w1.z) + (w2.z + w3.z);
        acc.w += (w0.w + w1.w) + (w2.w + w3.w);
    }
    for (; j < end; j++) {
        int u = g_csr[j];
        float4 w = *reinterpret_cast<const float4*>(feats + (size_t)u * D + t * 4);
        acc.x += w.x; acc.y += w.y; acc.z += w.z; acc.w += w.w;
    }
    __half2 h0 = __floats2half2_rn(acc.x, acc.y);
    __half2 h1 = __floats2half2_rn(acc.z, acc.w);
    __half2* dstp = reinterpret_cast<__half2*>(g_hh + (size_t)v * D + t * 4);
    dstp[0] = h0;
    dstp[1] = h1;
}

// ---------------- bucketed fp16 GEMM, ldmatrix frags, 3-stage cp.async, occ 2 ----
// x[node] = [h|feats](K=1024,fp16) @ Wt[d](fp16,[n][k]) + bl[d]; BN stats fused.
__global__ __launch_bounds__(256, 2)
void k_gemm(const float* __restrict__ bl) {
    int tileId = blockIdx.y;
    if (tileId >= g_ntiles) return;
    int d     = g_tile_bucket[tileId];
    int row0  = g_tile_row[tileId];
    int nrows = g_tile_rows[tileId];
    int n0    = blockIdx.x * TN;

    extern __shared__ float smem[];
    int* perm_s = (int*)(smem + SMEM_WORDS);
    uint32_t smem_u32 = (uint32_t)__cvta_generic_to_shared(smem);

    int tid  = threadIdx.x;
    int lane = tid & 31;
    int warp = tid >> 5;
    int grp  = lane >> 2;
    int tig  = lane & 3;
    int wrow0 = (warp & 1) * 64;
    int wcol0 = (warp >> 1) * 32;

    if (tid < TM) perm_s[tid] = (tid < nrows) ? g_perm[row0 + tid] : -1;
    __syncthreads();

    // per-thread load coordinates: 1024 chunks each for A and B (4/thread each)
    uint32_t a_s[4], b_s[4];
    size_t a_goff[4], b_goff[4];   // HALF-element offsets
    int a_valid[4];
#pragma unroll
    for (int p = 0; p < 4; p++) {
        int c = tid + p * 256;
        int row = c >> 3, ch = c & 7;      // 8 x 16B chunks per 64-half row
        int node = perm_s[row];
        a_valid[p] = (node >= 0) ? 16 : 0;
        if (node < 0) node = 0;
        a_goff[p] = (size_t)node * D + (size_t)(ch * 8);
        a_s[p] = (uint32_t)__cvta_generic_to_shared(
            &smem[row * PITCH + ch * 4]);
        b_goff[p] = ((size_t)d * D + (size_t)(n0 + row)) * KTOT + (size_t)(ch * 8);
        b_s[p] = (uint32_t)__cvta_generic_to_shared(
            &smem[A_WORDS + row * PITCH + ch * 4]);
    }

    auto load_stage = [&](int kk, int stg) {
        const __half* aptr = (kk < 512) ? g_hh : g_featsh;
        int kb = kk & 511;
        uint32_t soff = (uint32_t)(stg * (STAGE_WORDS * 4));
#pragma unroll
        for (int p = 0; p < 4; p++)
            cp_async16(a_s[p] + soff, aptr + a_goff[p] + kb, a_valid[p]);
#pragma unroll
        for (int p = 0; p < 4; p++)
            cp_async16(b_s[p] + soff, g_wth + b_goff[p] + kk, 16);
    };

    // ldmatrix per-thread byte offsets (within A / B regions)
    //   A x4 tiles: rows 0-7 k0 | rows 8-15 k0 | rows 0-7 k8 | rows 8-15 k8
    uint32_t a_lm = (uint32_t)((lane & 15) * (PITCH * 4) + (lane >> 4) * 16);
    //   B x4 tiles (per ni-pair): cols 0-7 k0 | cols 0-7 k8 | cols 8-15 k0 | cols 8-15 k8
    uint32_t b_lm = (uint32_t)(((lane & 7) + (lane >> 4) * 8) * (PITCH * 4) +
                               ((lane >> 3) & 1) * 16);

    float acc[4][4][4];
#pragma unroll
    for (int mi = 0; mi < 4; mi++)
#pragma unroll
        for (int ni = 0; ni < 4; ni++)
#pragma unroll
            for (int q = 0; q < 4; q++) acc[mi][ni][q] = 0.f;

    load_stage(0, 0); cp_commit();
    load_stage(TK, 1); cp_commit();

    const int NIT = KTOT / TK;   // 16
    int stage = 0;
#pragma unroll 1
    for (int kt = 0; kt < NIT; kt++) {
        cp_wait1();
        __syncthreads();
        if (kt + 2 < NIT) {
            int nstg = stage + 2; if (nstg >= STAGES) nstg -= STAGES;
            load_stage((kt + 2) * TK, nstg);
        }
        cp_commit();

        uint32_t As_addr = smem_u32 + (uint32_t)(stage * STAGE_WORDS * 4);
        uint32_t Bs_addr = As_addr + (uint32_t)(A_WORDS * 4);
#pragma unroll
        for (int s16 = 0; s16 < 4; s16++) {       // 4 k16 steps per 64-half stage
            uint32_t af[4][4], bf[4][2];
#pragma unroll
            for (int mi = 0; mi < 4; mi++)
                ldsm_x4(af[mi][0], af[mi][1], af[mi][2], af[mi][3],
                        As_addr + (uint32_t)((wrow0 + mi * 16) * (PITCH * 4)) +
                        a_lm + (uint32_t)(s16 * 32));
#pragma unroll
            for (int p = 0; p < 2; p++)
                ldsm_x4(bf[2 * p][0], bf[2 * p][1], bf[2 * p + 1][0],
                        bf[2 * p + 1][1],
                        Bs_addr + (uint32_t)((wcol0 + p * 16) * (PITCH * 4)) +
                        b_lm + (uint32_t)(s16 * 32));
#pragma unroll
            for (int mi = 0; mi < 4; mi++)
#pragma unroll
                for (int ni = 0; ni < 4; ni++)
                    mma_f16(acc[mi][ni], af[mi], bf[ni]);
        }
        stage = stage + 1; if (stage >= STAGES) stage = 0;
    }

    // epilogue: bias add, store, fused BN column sums
    float2 bias[4];
#pragma unroll
    for (int ni = 0; ni < 4; ni++)
        bias[ni] = *reinterpret_cast<const float2*>(
            bl + (size_t)d * D + n0 + wcol0 + ni * 8 + 2 * tig);

    float s_sum[4][2] = {}, s_sq[4][2] = {};
#pragma unroll
    for (int mi = 0; mi < 4; mi++) {
        int r0 = wrow0 + mi * 16 + grp;
        int node0 = perm_s[r0];
        int node1 = perm_s[r0 + 8];
#pragma unroll
        for (int ni = 0; ni < 4; ni++) {
            int cc = wcol0 + ni * 8 + 2 * tig;
            float v0x = acc[mi][ni][0] + bias[ni].x;
            float v0y = acc[mi][ni][1] + bias[ni].y;
            float v1x = acc[mi][ni][2] + bias[ni].x;
            float v1y = acc[mi][ni][3] + bias[ni].y;
            if (node0 >= 0) {
                float2 v; v.x = v0x; v.y = v0y;
                *reinterpret_cast<float2*>(g_x + (size_t)node0 * D + n0 + cc) = v;
                s_sum[ni][0] += v0x; s_sq[ni][0] += v0x * v0x;
                s_sum[ni][1] += v0y; s_sq[ni][1] += v0y * v0y;
            }
            if (node1 >= 0) {
                float2 v; v.x = v1x; v.y = v1y;
                *reinterpret_cast<float2*>(g_x + (size_t)node1 * D + n0 + cc) = v;
                s_sum[ni][0] += v1x; s_sq[ni][0] += v1x * v1x;
                s_sum[ni][1] += v1y; s_sq[ni][1] += v1y * v1y;
            }
        }
    }
#pragma unroll
    for (int ni = 0; ni < 4; ni++)
#pragma unroll
        for (int b = 0; b < 2; b++) {
            float s = s_sum[ni][b], q = s_sq[ni][b];
#pragma unroll
            for (int off = 4; off < 32; off <<= 1) {
                s += __shfl_xor_sync(0xffffffffu, s, off);
                q += __shfl_xor_sync(0xffffffffu, q, off);
            }
            if (grp == 0) {
                int c = n0 + wcol0 + ni * 8 + 2 * tig + b;
                atomicAdd(&g_sum[c], s);
                atomicAdd(&g_sumsq[c], q);
            }
        }
}

// ---------------- BN finalize -----------------------------------------------------
__global__ void k_finalize(int n, const float* __restrict__ gamma,
                           const float* __restrict__ beta) {
    int c = threadIdx.x;
    float invn = 1.f / (float)n;
    float mean = g_sum[c] * invn;
    float var  = g_sumsq[c] * invn - mean * mean;
    float s    = gamma[c] * rsqrtf(var + BN_EPS);
    g_scale[c] = s;
    g_shift[c] = beta[c] - mean * s;
}

// ---------------- max aggregation (BN affine fused, sign-safe) ---------------------
__global__ void k_maxagg(float* __restrict__ out) {
    int v = blockIdx.x;
    int t = threadIdx.x;
    float4 mx = *reinterpret_cast<const float4*>(g_x + (size_t)v * D + t * 4);
    float4 mn = mx;
    int beg = g_off[v], end = g_off[v + 1];
    int j = beg;
    for (; j + 4 <= end; j += 4) {
        int u0 = g_csr[j], u1 = g_csr[j + 1], u2 = g_csr[j + 2], u3 = g_csr[j + 3];
        float4 w0 = *reinterpret_cast<const float4*>(g_x + (size_t)u0 * D + t * 4);
        float4 w1 = *reinterpret_cast<const float4*>(g_x + (size_t)u1 * D + t * 4);
        float4 w2 = *reinterpret_cast<const float4*>(g_x + (size_t)u2 * D + t * 4);
        float4 w3 = *reinterpret_cast<const float4*>(g_x + (size_t)u3 * D + t * 4);
        float hx = fmaxf(fmaxf(w0.x, w1.x), fmaxf(w2.x, w3.x));
        float lx = fminf(fminf(w0.x, w1.x), fminf(w2.x, w3.x));
        float hy = fmaxf(fmaxf(w0.y, w1.y), fmaxf(w2.y, w3.y));
        float ly = fminf(fminf(w0.y, w1.y), fminf(w2.y, w3.y));
        float hz = fmaxf(fmaxf(w0.z, w1.z), fmaxf(w2.z, w3.z));
        float lz = fminf(fminf(w0.z, w1.z), fminf(w2.z, w3.z));
        float hw = fmaxf(fmaxf(w0.w, w1.w), fmaxf(w2.w, w3.w));
        float lw = fminf(fminf(w0.w, w1.w), fminf(w2.w, w3.w));
        mx.x = fmaxf(mx.x, hx); mn.x = fminf(mn.x, lx);
        mx.y = fmaxf(mx.y, hy); mn.y = fminf(mn.y, ly);
        mx.z = fmaxf(mx.z, hz); mn.z = fminf(mn.z, lz);
        mx.w = fmaxf(mx.w, hw); mn.w = fminf(mn.w, lw);
    }
    for (; j < end; j++) {
        int u = g_csr[j];
        float4 w = *reinterpret_cast<const float4*>(g_x + (size_t)u * D + t * 4);
        mx.x = fmaxf(mx.x, w.x); mn.x = fminf(mn.x, w.x);
        mx.y = fmaxf(mx.y, w.y); mn.y = fminf(mn.y, w.y);
        mx.z = fmaxf(mx.z, w.z); mn.z = fminf(mn.z, w.z);
        mx.w = fmaxf(mx.w, w.w); mn.w = fminf(mn.w, w.w);
    }
    float4 sc = reinterpret_cast<const float4*>(g_scale)[t];
    float4 sh = reinterpret_cast<const float4*>(g_shift)[t];
    float4 r;
    r.x = (sc.x >= 0.f ? mx.x : mn.x) * sc.x + sh.x;
    r.y = (sc.y >= 0.f ? mx.y : mn.y) * sc.y + sh.y;
    r.z = (sc.z >= 0.f ? mx.z : mn.z) * sc.z + sh.z;
    r.w = (sc.w >= 0.f ? mx.w : mn.w) * sc.w + sh.w;
    reinterpret_cast<float4*>(out + (size_t)v * D)[t] = r;
}

// ---------------- launch -------------------------------------------------------------
extern "C" void kernel_launch(void* const* d_in, const int* in_sizes, int n_in,
                              void* d_out, int out_size) {
    const float* feats = (const float*)d_in[0];
    const int*   src   = (const int*)d_in[1];
    const int*   dst   = (const int*)d_in[2];
    const float* Wl    = (const float*)d_in[3];
    const float* Wr    = (const float*)d_in[4];
    const float* bl    = (const float*)d_in[5];
    const float* gamma = (const float*)d_in[6];
    const float* beta  = (const float*)d_in[7];
    float* out = (float*)d_out;

    int n = in_sizes[0] / D;
    int e = in_sizes[1];

    cudaFuncSetAttribute(k_gemm, cudaFuncAttributeMaxDynamicSharedMemorySize,
                         SMEM_BYTES);

    k_zero<<<(n + 255) / 256, 256>>>(n);
    k_prepack<<<dim3(D / 32, KTOT / 32, NBUK), dim3(32, 8)>>>(Wl, Wr);
    k_cvt<<<(n * (D / 4) + 255) / 256, 256>>>(feats, n * (D / 4));
    k_degcount<<<(e + 255) / 256, 256>>>(dst, e);
    k_scan<<<1, 1024>>>(n);
    k_fill<<<(e + n + 255) / 256, 256>>>(src, dst, e, n);
    k_nbrsum<<<n, 128>>>(feats);
    k_gemm<<<dim3(D / TN, MAXT), 256, SMEM_BYTES>>>(bl);
    k_finalize<<<1, D>>>(n, gamma, beta);
    k_maxagg<<<n, 128>>>(out);
}

// round 11
// speedup vs baseline: 1.4795x; 1.0584x over previous
#include <cuda_runtime.h>
#include <cuda_fp16.h>
#include <cstdint>

#define NMAX   20000
#define EMAX   160000
#define D      512
#define KTOT   1024
#define NBUK   11
#define TM     128
#define MAXT   ((NMAX + TM - 1) / TM + NBUK)   // 168
#define BN_EPS 1e-5f

#define TN  128
#define TK  64      // halfs of K per stage
#define PITCH 36    // words per 64-half row (128B data + 16B pad): conflict-free
#define A_WORDS (TM * PITCH)             // 4608
#define B_WORDS (TN * PITCH)             // 4608
#define STAGES 3
#define STAGE_WORDS (A_WORDS + B_WORDS)  // 9216 words = 36864 B
#define SMEM_WORDS (STAGES * STAGE_WORDS)
#define SMEM_BYTES (SMEM_WORDS*4 + TM*4) // + perm_s = 111104 B (2 CTAs/SM fit)

// ---------------- scratch (device globals; no allocation allowed) -------------
__device__ int    g_deg[NMAX];
__device__ int    g_off[NMAX + 1];
__device__ int    g_cur[NMAX];
__device__ int    g_csr[EMAX];
__device__ int    g_bcnt[NBUK];
__device__ int    g_boff[NBUK + 1];
__device__ int    g_bcur[NBUK];
__device__ int    g_perm[NMAX];
__device__ int    g_tile_bucket[MAXT];
__device__ int    g_tile_row[MAXT];
__device__ int    g_tile_rows[MAXT];
__device__ int    g_ntiles;
__device__ __half g_hh[(size_t)NMAX * D];        // neighbor sums (fp16)
__device__ __half g_featsh[(size_t)NMAX * D];    // feats (fp16)
__device__ __half g_xh[(size_t)NMAX * D];        // pre-BN linear output (fp16)
__device__ __half g_wth[(size_t)NBUK * D * KTOT];// packed fp16 weights [d][n][k]
__device__ float  g_sum[D], g_sumsq[D], g_scale[D], g_shift[D];

// ---------------- helpers -----------------------------------------------------
__device__ __forceinline__ void mma_f16(float c[4], const uint32_t a[4],
                                        const uint32_t b[2]) {
    asm volatile(
        "mma.sync.aligned.m16n8k16.row.col.f32.f16.f16.f32 "
        "{%0,%1,%2,%3}, {%4,%5,%6,%7}, {%8,%9}, {%0,%1,%2,%3};\n"
        : "+f"(c[0]), "+f"(c[1]), "+f"(c[2]), "+f"(c[3])
        : "r"(a[0]), "r"(a[1]), "r"(a[2]), "r"(a[3]), "r"(b[0]), "r"(b[1]));
}

__device__ __forceinline__ void ldsm_x4(uint32_t& d0, uint32_t& d1,
                                        uint32_t& d2, uint32_t& d3,
                                        uint32_t saddr) {
    asm volatile("ldmatrix.sync.aligned.m8n8.x4.shared.b16 {%0,%1,%2,%3}, [%4];"
                 : "=r"(d0), "=r"(d1), "=r"(d2), "=r"(d3) : "r"(saddr));
}

__device__ __forceinline__ void cp_async16(uint32_t saddr, const void* gaddr,
                                           int src_bytes) {
    asm volatile("cp.async.cg.shared.global [%0], [%1], 16, %2;\n"
                 :: "r"(saddr), "l"(gaddr), "r"(src_bytes));
}
__device__ __forceinline__ void cp_commit() {
    asm volatile("cp.async.commit_group;\n");
}
__device__ __forceinline__ void cp_wait1() {
    asm volatile("cp.async.wait_group 1;\n");
}

// ---------------- setup kernels ------------------------------------------------
__global__ void k_zero(int n) {
    int i = blockIdx.x * blockDim.x + threadIdx.x;
    if (i < n) g_deg[i] = 0;
    if (i < D) { g_sum[i] = 0.f; g_sumsq[i] = 0.f; }
    if (i < NBUK) { g_bcnt[i] = 0; g_bcur[i] = 0; }
}

// weights fp32 [d][k][n] -> fp16 [d][n][k] (transposed)
__global__ void k_prepack(const float* __restrict__ Wl,
                          const float* __restrict__ Wr) {
    __shared__ float s[32][33];
    int d  = blockIdx.z;
    int nt = blockIdx.x * 32;
    int kt = blockIdx.y * 32;     // 0..1023
    int tx = threadIdx.x, ty = threadIdx.y;
    const float* Wsrc = (kt < 512) ? Wl : Wr;
    int kb = kt & 511;
#pragma unroll
    for (int i = 0; i < 4; i++)
        s[ty + i * 8][tx] = Wsrc[((size_t)d * 512 + kb + ty + i * 8) * D + nt + tx];
    __syncthreads();
#pragma unroll
    for (int i = 0; i < 4; i++) {
        int nn = nt + ty + i * 8;
        g_wth[((size_t)d * D + nn) * KTOT + kt + tx] = __float2half(s[tx][ty + i * 8]);
    }
}

// feats fp32 -> fp16, merged with degree count
__global__ void k_cvtdeg(const float* __restrict__ feats,
                         const int* __restrict__ dst, int total4, int e) {
    int i = blockIdx.x * blockDim.x + threadIdx.x;
    if (i < total4) {
        float4 f = reinterpret_cast<const float4*>(feats)[i];
        __half2 h0 = __floats2half2_rn(f.x, f.y);
        __half2 h1 = __floats2half2_rn(f.z, f.w);
        reinterpret_cast<__half2*>(g_featsh)[i * 2]     = h0;
        reinterpret_cast<__half2*>(g_featsh)[i * 2 + 1] = h1;
    }
    if (i < e) atomicAdd(&g_deg[dst[i]], 1);
}

// scan (warp-shuffle based) + bucket histogram + tile map, one block
__global__ void k_scan(int n) {
    __shared__ int wsum[32];
    __shared__ int bc[NBUK];
    int t = threadIdx.x, lane = t & 31, w = t >> 5;
    if (t < NBUK) bc[t] = 0;
    int carry = 0;
    int nchunk = (n + 1023) >> 10;
    for (int ch = 0; ch < nchunk; ch++) {
        int i = ch * 1024 + t;
        int v = (i < n) ? g_deg[i] : 0;
        int x = v;
#pragma unroll
        for (int o = 1; o < 32; o <<= 1) {
            int y = __shfl_up_sync(0xffffffffu, x, o);
            if (lane >= o) x += y;
        }
        if (lane == 31) wsum[w] = x;
        __syncthreads();
        if (w == 0) {
            int s = wsum[lane];
#pragma unroll
            for (int o = 1; o < 32; o <<= 1) {
                int y = __shfl_up_sync(0xffffffffu, s, o);
                if (lane >= o) s += y;
            }
            wsum[lane] = s;
        }
        __syncthreads();
        int prev = (w > 0) ? wsum[w - 1] : 0;
        if (i < n) {
            int ex = carry + prev + x - v;
            g_off[i] = ex;
            g_cur[i] = ex;
        }
        carry += wsum[31];
        __syncthreads();
    }
    if (t == 0) g_off[n] = carry;
    for (int i = t; i < n; i += 1024) {
        int dd = g_deg[i];
        if (dd > NBUK - 1) dd = NBUK - 1;
        atomicAdd(&bc[dd], 1);
    }
    __syncthreads();
    if (t == 0) {
        int acc = 0;
        for (int dd = 0; dd < NBUK; dd++) {
            g_bcnt[dd] = bc[dd];
            g_boff[dd] = acc;
            acc += bc[dd];
        }
        g_boff[NBUK] = acc;
        int tt = 0;
        for (int dd = 0; dd < NBUK; dd++) {
            int c = bc[dd], o = g_boff[dd];
            for (int r = 0; r < c; r += TM) {
                g_tile_bucket[tt] = dd;
                g_tile_row[tt]    = o + r;
                g_tile_rows[tt]   = (c - r < TM) ? (c - r) : TM;
                tt++;
            }
        }
        g_ntiles = tt;
    }
}

// CSR fill + bucket fill (merged)
__global__ void k_fill(const int* __restrict__ src, const int* __restrict__ dst,
                       int e, int n) {
    int i = blockIdx.x * blockDim.x + threadIdx.x;
    if (i < e) {
        int pos = atomicAdd(&g_cur[dst[i]], 1);
        g_csr[pos] = src[i];
    }
    int v = i - e;
    if (v >= 0 && v < n) {
        int dd = g_deg[v];
        if (dd > NBUK - 1) dd = NBUK - 1;
        int pos = g_boff[dd] + atomicAdd(&g_bcur[dd], 1);
        g_perm[pos] = v;
    }
}

// ---------------- neighbor sum: fp16 gather, fp32 acc, fp16 out --------------------
__global__ void k_nbrsum() {
    int v = blockIdx.x;
    int t = threadIdx.x;             // 128 threads, each 4 halfs (uint2)
    const uint2* F = reinterpret_cast<const uint2*>(g_featsh);
    float2 a0 = make_float2(0.f, 0.f), a1 = make_float2(0.f, 0.f);
    int beg = g_off[v], end = g_off[v + 1];
    int j = beg;
#define ACC_H(wu) { \
        __half2 p0 = *reinterpret_cast<__half2*>(&(wu).x); \
        __half2 p1 = *reinterpret_cast<__half2*>(&(wu).y); \
        float2 f0 = __half22float2(p0); \
        float2 f1 = __half22float2(p1); \
        a0.x += f0.x; a0.y += f0.y; a1.x += f1.x; a1.y += f1.y; }
    for (; j + 4 <= end; j += 4) {
        int u0 = g_csr[j], u1 = g_csr[j + 1], u2 = g_csr[j + 2], u3 = g_csr[j + 3];
        uint2 w0 = F[(size_t)u0 * (D / 4) + t];
        uint2 w1 = F[(size_t)u1 * (D / 4) + t];
        uint2 w2 = F[(size_t)u2 * (D / 4) + t];
        uint2 w3 = F[(size_t)u3 * (D / 4) + t];
        ACC_H(w0); ACC_H(w1); ACC_H(w2); ACC_H(w3);
    }
    for (; j < end; j++) {
        int u = g_csr[j];
        uint2 w = F[(size_t)u * (D / 4) + t];
        ACC_H(w);
    }
#undef ACC_H
    __half2 h0 = __floats2half2_rn(a0.x, a0.y);
    __half2 h1 = __floats2half2_rn(a1.x, a1.y);
    uint2 o;
    o.x = *reinterpret_cast<uint32_t*>(&h0);
    o.y = *reinterpret_cast<uint32_t*>(&h1);
    reinterpret_cast<uint2*>(g_hh)[(size_t)v * (D / 4) + t] = o;
}

// ---------------- bucketed fp16 GEMM, ldmatrix frags, 3-stage cp.async, occ 2 ----
// x[node] = [h|feats](K=1024,fp16) @ Wt[d](fp16,[n][k]) + bl[d]; BN stats fused.
__global__ __launch_bounds__(256, 2)
void k_gemm(const float* __restrict__ bl) {
    int tileId = blockIdx.y;
    if (tileId >= g_ntiles) return;
    int d     = g_tile_bucket[tileId];
    int row0  = g_tile_row[tileId];
    int nrows = g_tile_rows[tileId];
    int n0    = blockIdx.x * TN;

    extern __shared__ float smem[];
    int* perm_s = (int*)(smem + SMEM_WORDS);
    uint32_t smem_u32 = (uint32_t)__cvta_generic_to_shared(smem);

    int tid  = threadIdx.x;
    int lane = tid & 31;
    int warp = tid >> 5;
    int grp  = lane >> 2;
    int tig  = lane & 3;
    int wrow0 = (warp & 1) * 64;
    int wcol0 = (warp >> 1) * 32;

    if (tid < TM) perm_s[tid] = (tid < nrows) ? g_perm[row0 + tid] : -1;
    __syncthreads();

    // per-thread load coordinates: 1024 chunks each for A and B (4/thread each)
    uint32_t a_s[4], b_s[4];
    size_t a_goff[4], b_goff[4];   // HALF-element offsets
    int a_valid[4];
#pragma unroll
    for (int p = 0; p < 4; p++) {
        int c = tid + p * 256;
        int row = c >> 3, ch = c & 7;      // 8 x 16B chunks per 64-half row
        int node = perm_s[row];
        a_valid[p] = (node >= 0) ? 16 : 0;
        if (node < 0) node = 0;
        a_goff[p] = (size_t)node * D + (size_t)(ch * 8);
        a_s[p] = (uint32_t)__cvta_generic_to_shared(
            &smem[row * PITCH + ch * 4]);
        b_goff[p] = ((size_t)d * D + (size_t)(n0 + row)) * KTOT + (size_t)(ch * 8);
        b_s[p] = (uint32_t)__cvta_generic_to_shared(
            &smem[A_WORDS + row * PITCH + ch * 4]);
    }

    auto load_stage = [&](int kk, int stg) {
        const __half* aptr = (kk < 512) ? g_hh : g_featsh;
        int kb = kk & 511;
        uint32_t soff = (uint32_t)(stg * (STAGE_WORDS * 4));
#pragma unroll
        for (int p = 0; p < 4; p++)
            cp_async16(a_s[p] + soff, aptr + a_goff[p] + kb, a_valid[p]);
#pragma unroll
        for (int p = 0; p < 4; p++)
            cp_async16(b_s[p] + soff, g_wth + b_goff[p] + kk, 16);
    };

    // ldmatrix per-thread byte offsets (within A / B regions)
    uint32_t a_lm = (uint32_t)((lane & 15) * (PITCH * 4) + (lane >> 4) * 16);
    uint32_t b_lm = (uint32_t)(((lane & 7) + (lane >> 4) * 8) * (PITCH * 4) +
                               ((lane >> 3) & 1) * 16);

    float acc[4][4][4];
#pragma unroll
    for (int mi = 0; mi < 4; mi++)
#pragma unroll
        for (int ni = 0; ni < 4; ni++)
#pragma unroll
            for (int q = 0; q < 4; q++) acc[mi][ni][q] = 0.f;

    load_stage(0, 0); cp_commit();
    load_stage(TK, 1); cp_commit();

    const int NIT = KTOT / TK;   // 16
    int stage = 0;
#pragma unroll 1
    for (int kt = 0; kt < NIT; kt++) {
        cp_wait1();
        __syncthreads();
        if (kt + 2 < NIT) {
            int nstg = stage + 2; if (nstg >= STAGES) nstg -= STAGES;
            load_stage((kt + 2) * TK, nstg);
        }
        cp_commit();

        uint32_t As_addr = smem_u32 + (uint32_t)(stage * STAGE_WORDS * 4);
        uint32_t Bs_addr = As_addr + (uint32_t)(A_WORDS * 4);
#pragma unroll
        for (int s16 = 0; s16 < 4; s16++) {       // 4 k16 steps per 64-half stage
            uint32_t af[4][4], bf[4][2];
#pragma unroll
            for (int mi = 0; mi < 4; mi++)
                ldsm_x4(af[mi][0], af[mi][1], af[mi][2], af[mi][3],
                        As_addr + (uint32_t)((wrow0 + mi * 16) * (PITCH * 4)) +
                        a_lm + (uint32_t)(s16 * 32));
#pragma unroll
            for (int p = 0; p < 2; p++)
                ldsm_x4(bf[2 * p][0], bf[2 * p][1], bf[2 * p + 1][0],
                        bf[2 * p + 1][1],
                        Bs_addr + (uint32_t)((wcol0 + p * 16) * (PITCH * 4)) +
                        b_lm + (uint32_t)(s16 * 32));
#pragma unroll
            for (int mi = 0; mi < 4; mi++)
#pragma unroll
                for (int ni = 0; ni < 4; ni++)
                    mma_f16(acc[mi][ni], af[mi], bf[ni]);
        }
        stage = stage + 1; if (stage >= STAGES) stage = 0;
    }

    // epilogue: bias add, fp16 store, fused BN column sums (fp32-exact)
    float2 bias[4];
#pragma unroll
    for (int ni = 0; ni < 4; ni++)
        bias[ni] = *reinterpret_cast<const float2*>(
            bl + (size_t)d * D + n0 + wcol0 + ni * 8 + 2 * tig);

    float s_sum[4][2] = {}, s_sq[4][2] = {};
#pragma unroll
    for (int mi = 0; mi < 4; mi++) {
        int r0 = wrow0 + mi * 16 + grp;
        int node0 = perm_s[r0];
        int node1 = perm_s[r0 + 8];
#pragma unroll
        for (int ni = 0; ni < 4; ni++) {
            int cc = wcol0 + ni * 8 + 2 * tig;
            float v0x = acc[mi][ni][0] + bias[ni].x;
            float v0y = acc[mi][ni][1] + bias[ni].y;
            float v1x = acc[mi][ni][2] + bias[ni].x;
            float v1y = acc[mi][ni][3] + bias[ni].y;
            if (node0 >= 0) {
                __half2 h = __floats2half2_rn(v0x, v0y);
                *reinterpret_cast<uint32_t*>(g_xh + (size_t)node0 * D + n0 + cc) =
                    *reinterpret_cast<uint32_t*>(&h);
                s_sum[ni][0] += v0x; s_sq[ni][0] += v0x * v0x;
                s_sum[ni][1] += v0y; s_sq[ni][1] += v0y * v0y;
            }
            if (node1 >= 0) {
                __half2 h = __floats2half2_rn(v1x, v1y);
                *reinterpret_cast<uint32_t*>(g_xh + (size_t)node1 * D + n0 + cc) =
                    *reinterpret_cast<uint32_t*>(&h);
                s_sum[ni][0] += v1x; s_sq[ni][0] += v1x * v1x;
                s_sum[ni][1] += v1y; s_sq[ni][1] += v1y * v1y;
            }
        }
    }
#pragma unroll
    for (int ni = 0; ni < 4; ni++)
#pragma unroll
        for (int b = 0; b < 2; b++) {
            float s = s_sum[ni][b], q = s_sq[ni][b];
#pragma unroll
            for (int off = 4; off < 32; off <<= 1) {
                s += __shfl_xor_sync(0xffffffffu, s, off);
                q += __shfl_xor_sync(0xffffffffu, q, off);
            }
            if (grp == 0) {
                int c = n0 + wcol0 + ni * 8 + 2 * tig + b;
                atomicAdd(&g_sum[c], s);
                atomicAdd(&g_sumsq[c], q);
            }
        }
}

// ---------------- BN finalize -----------------------------------------------------
__global__ void k_finalize(int n, const float* __restrict__ gamma,
                           const float* __restrict__ beta) {
    int c = threadIdx.x;
    float invn = 1.f / (float)n;
    float mean = g_sum[c] * invn;
    float var  = g_sumsq[c] * invn - mean * mean;
    float s    = gamma[c] * rsqrtf(var + BN_EPS);
    g_scale[c] = s;
    g_shift[c] = beta[c] - mean * s;
}

// ---------------- max aggregation: fp16 gather, exact hmax/hmin, BN fused ----------
__global__ void k_maxagg(float* __restrict__ out) {
    int v = blockIdx.x;
    int t = threadIdx.x;             // 128 threads, each 4 halfs (uint2)
    const uint2* X = reinterpret_cast<const uint2*>(g_xh);
    uint2 s0 = X[(size_t)v * (D / 4) + t];
    __half2 mx0 = *reinterpret_cast<__half2*>(&s0.x);
    __half2 mx1 = *reinterpret_cast<__half2*>(&s0.y);
    __half2 mn0 = mx0, mn1 = mx1;
    int beg = g_off[v], end = g_off[v + 1];
    int j = beg;
#define ACC_MM(wu) { \
        __half2 p0 = *reinterpret_cast<__half2*>(&(wu).x); \
        __half2 p1 = *reinterpret_cast<__half2*>(&(wu).y); \
        mx0 = __hmax2(mx0, p0); mn0 = __hmin2(mn0, p0); \
        mx1 = __hmax2(mx1, p1); mn1 = __hmin2(mn1, p1); }
    for (; j + 4 <= end; j += 4) {
        int u0 = g_csr[j], u1 = g_csr[j + 1], u2 = g_csr[j + 2], u3 = g_csr[j + 3];
        uint2 w0 = X[(size_t)u0 * (D / 4) + t];
        uint2 w1 = X[(size_t)u1 * (D / 4) + t];
        uint2 w2 = X[(size_t)u2 * (D / 4) + t];
        uint2 w3 = X[(size_t)u3 * (D / 4) + t];
        ACC_MM(w0); ACC_MM(w1); ACC_MM(w2); ACC_MM(w3);
    }
    for (; j < end; j++) {
        int u = g_csr[j];
        uint2 w = X[(size_t)u * (D / 4) + t];
        ACC_MM(w);
    }
#undef ACC_MM
    float2 fmx0 = __half22float2(mx0), fmx1 = __half22float2(mx1);
    float2 fmn0 = __half22float2(mn0), fmn1 = __half22float2(mn1);
    float4 sc = reinterpret_cast<const float4*>(g_scale)[t];
    float4 sh = reinterpret_cast<const float4*>(g_shift)[t];
    float4 r;
    r.x = (sc.x >= 0.f ? fmx0.x : fmn0.x) * sc.x + sh.x;
    r.y = (sc.y >= 0.f ? fmx0.y : fmn0.y) * sc.y + sh.y;
    r.z = (sc.z >= 0.f ? fmx1.x : fmn1.x) * sc.z + sh.z;
    r.w = (sc.w >= 0.f ? fmx1.y : fmn1.y) * sc.w + sh.w;
    reinterpret_cast<float4*>(out + (size_t)v * D)[t] = r;
}

// ---------------- launch -------------------------------------------------------------
extern "C" void kernel_launch(void* const* d_in, const int* in_sizes, int n_in,
                              void* d_out, int out_size) {
    const float* feats = (const float*)d_in[0];
    const int*   src   = (const int*)d_in[1];
    const int*   dst   = (const int*)d_in[2];
    const float* Wl    = (const float*)d_in[3];
    const float* Wr    = (const float*)d_in[4];
    const float* bl    = (const float*)d_in[5];
    const float* gamma = (const float*)d_in[6];
    const float* beta  = (const float*)d_in[7];
    float* out = (float*)d_out;

    int n = in_sizes[0] / D;
    int e = in_sizes[1];
    int total4 = n * (D / 4);

    cudaFuncSetAttribute(k_gemm, cudaFuncAttributeMaxDynamicSharedMemorySize,
                         SMEM_BYTES);

    k_zero<<<(n + 255) / 256, 256>>>(n);
    k_prepack<<<dim3(D / 32, KTOT / 32, NBUK), dim3(32, 8)>>>(Wl, Wr);
    int big = total4 > e ? total4 : e;
    k_cvtdeg<<<(big + 255) / 256, 256>>>(feats, dst, total4, e);
    k_scan<<<1, 1024>>>(n);
    k_fill<<<(e + n + 255) / 256, 256>>>(src, dst, e, n);
    k_nbrsum<<<n, 128>>>();
    k_gemm<<<dim3(D / TN, MAXT), 256, SMEM_BYTES>>>(bl);
    k_finalize<<<1, D>>>(n, gamma, beta);
    k_maxagg<<<n, 128>>>(out);
}